// round 14
// baseline (speedup 1.0000x reference)
#include <cuda_runtime.h>
#include <cuda_fp16.h>
#include <math.h>
#include <stdint.h>

// TriangleMultiplication: N=768, C=128 — fp16 tensor-core pipeline + cp.async + ldmatrix
//   k_cvtw         : weights -> fp16
//   k_ln1          : x = LN(pair)                            -> g_xh [r][c] fp16
//   k_projgate_mma : a,b = split((x@Wp^T)*mask*sig(x@Wg^T))  -> ga,gb [c][r] fp16
//   k_einsum_mma   : out_c = A_c @ B_c^T per channel (fp16, 128x256 tile, 64x64 warps) -> g_o
//   k_ln2t         : u = LN_c(out) transposed                -> u (= g_ab reuse) fp16 [r][c]
//   k_final_mma    : out = (u@Wo^T) * sig(x@Wgat^T) (fp16)   -> d_out f32

#define NTOK 768
#define CH   128
#define RTOT (NTOK*NTOK)   // 589824

__device__ __half g_xh[(size_t)RTOT*CH];
__device__ float  g_o[(size_t)CH*RTOT];
__device__ __align__(256) unsigned char g_ab[(size_t)CH*RTOT*4];
__device__ __half g_wh[768*CH];

__device__ __forceinline__ float sigm(float v){ return 1.f/(1.f+expf(-v)); }

__device__ __forceinline__ void mma16(float* d, const uint32_t* a, const uint32_t* b){
    asm volatile(
        "mma.sync.aligned.m16n8k16.row.col.f32.f16.f16.f32 "
        "{%0,%1,%2,%3}, {%4,%5,%6,%7}, {%8,%9}, {%0,%1,%2,%3};"
        : "+f"(d[0]), "+f"(d[1]), "+f"(d[2]), "+f"(d[3])
        : "r"(a[0]), "r"(a[1]), "r"(a[2]), "r"(a[3]), "r"(b[0]), "r"(b[1]));
}

__device__ __forceinline__ void ldsm4(uint32_t* r, const __half* p){
    uint32_t a;
    asm("{ .reg .u64 t; cvta.to.shared.u64 t, %1; cvt.u32.u64 %0, t; }" : "=r"(a) : "l"(p));
    asm volatile("ldmatrix.sync.aligned.m8n8.x4.shared.b16 {%0,%1,%2,%3}, [%4];"
        : "=r"(r[0]), "=r"(r[1]), "=r"(r[2]), "=r"(r[3]) : "r"(a));
}

__device__ __forceinline__ uint4 h8pack(float4 lo, float4 hi){
    uint4 r;
    __half2 a = __floats2half2_rn(lo.x, lo.y);
    __half2 b = __floats2half2_rn(lo.z, lo.w);
    __half2 c = __floats2half2_rn(hi.x, hi.y);
    __half2 d = __floats2half2_rn(hi.z, hi.w);
    r.x = *(uint32_t*)&a;
    r.y = *(uint32_t*)&b;
    r.z = *(uint32_t*)&c;
    r.w = *(uint32_t*)&d;
    return r;
}
__device__ __forceinline__ uint2 h4pack(float4 v){
    uint2 r;
    __half2 a = __floats2half2_rn(v.x, v.y);
    __half2 b = __floats2half2_rn(v.z, v.w);
    r.x = *(uint32_t*)&a;
    r.y = *(uint32_t*)&b;
    return r;
}

__device__ __forceinline__ void cpa16(__half* dst, const __half* src){
    uint32_t s;
    asm("{ .reg .u64 t; cvta.to.shared.u64 t, %1; cvt.u32.u64 %0, t; }" : "=r"(s) : "l"(dst));
    asm volatile("cp.async.cg.shared.global [%0], [%1], 16;" :: "r"(s), "l"(src));
}
#define CPA_COMMIT() asm volatile("cp.async.commit_group;" ::: "memory")
#define CPA_WAIT0()  asm volatile("cp.async.wait_group 0;" ::: "memory")
#define CPA_WAIT1()  asm volatile("cp.async.wait_group 1;" ::: "memory")

#define HSTRIDE 72
#define HBUF (128*HSTRIDE)

__device__ __forceinline__ int a_lane_off(int lane){
    return ((lane & 7) + ((lane >> 3) & 1) * 8) * HSTRIDE + (lane >> 4) * 8;
}
__device__ __forceinline__ int b_lane_off(int lane){
    return ((lane & 7) + (lane >> 4) * 8) * HSTRIDE + ((lane >> 3) & 1) * 8;
}

// ---------------------------------------------------------------- weight convert
__global__ void k_cvtw(const float* __restrict__ projw, const float* __restrict__ gatew,
                       const float* __restrict__ outw,  const float* __restrict__ gatingw)
{
    int idx = blockIdx.x*256 + threadIdx.x;
    int row = idx >> 4, q8 = idx & 15;
    const float* src;
    if (row < 512) {
        int c = row >> 2, q = row & 3;
        src = (q < 2) ? projw + (size_t)(2*c+q)*CH : gatew + (size_t)(2*c+q-2)*CH;
    } else if (row < 640) {
        src = outw + (size_t)(row-512)*CH;
    } else {
        src = gatingw + (size_t)(row-640)*CH;
    }
    float4 lo = *(const float4*)(src + q8*8);
    float4 hi = *(const float4*)(src + q8*8 + 4);
    *(uint4*)(g_wh + (size_t)row*CH + q8*8) = h8pack(lo, hi);
}

// ---------------------------------------------------------------- LN1 -> fp16 x
__global__ void k_ln1(const float* __restrict__ pair,
                      const float* __restrict__ w,
                      const float* __restrict__ b)
{
    int warp = threadIdx.x >> 5, lane = threadIdx.x & 31;
    size_t r = (size_t)blockIdx.x * 8 + warp;
    const float4* src = (const float4*)(pair + r * CH);
    float4 v = src[lane];
    float s = v.x + v.y + v.z + v.w;
    #pragma unroll
    for (int o = 16; o; o >>= 1) s += __shfl_xor_sync(0xffffffffu, s, o);
    float mu = s * (1.f/128.f);
    float dx = v.x-mu, dy = v.y-mu, dz = v.z-mu, dw = v.w-mu;
    float q = dx*dx + dy*dy + dz*dz + dw*dw;
    #pragma unroll
    for (int o = 16; o; o >>= 1) q += __shfl_xor_sync(0xffffffffu, q, o);
    float rstd = rsqrtf(q * (1.f/128.f) + 1e-5f);
    float4 wv = ((const float4*)w)[lane];
    float4 bv = ((const float4*)b)[lane];
    float4 o4;
    o4.x = dx*rstd*wv.x + bv.x;
    o4.y = dy*rstd*wv.y + bv.y;
    o4.z = dz*rstd*wv.z + bv.z;
    o4.w = dw*rstd*wv.w + bv.w;
    *(uint2*)(g_xh + r * CH + lane*4) = h4pack(o4);
}

// ---------------------------------------------------------------- proj+gate (fp16 mma + cp.async + ldmatrix)
#define PG_SMEM (4*HBUF*2)   // 73728 B

__global__ void __launch_bounds__(256, 2) k_projgate_mma(const float* __restrict__ mask)
{
    extern __shared__ __half hsm[];
    __shared__ float m_s[128];
    int tid = threadIdx.x, lane = tid & 31, warp = tid >> 5;
    int cg = blockIdx.x;
    size_t i0 = (size_t)blockIdx.y * 128;
    const __half* A = g_xh + i0 * CH;
    __half* ga = (__half*)g_ab;
    __half* gb = ga + (size_t)CH*RTOT;

    if (tid < 128) m_s[tid] = mask[(int)(i0 % NTOK) + tid];

    int wm = (warp >> 2) * 64;
    int wn = (warp & 3) * 32;

    float acc[4][4][4];
    #pragma unroll
    for (int mt = 0; mt < 4; mt++)
        #pragma unroll
        for (int nt = 0; nt < 4; nt++)
            #pragma unroll
            for (int e = 0; e < 4; e++) acc[mt][nt][e] = 0.f;

    int rr = tid >> 3, q8 = tid & 7;
    const __half* W = g_wh + (size_t)(cg*128) * CH;

    {
        __half* dX = hsm;
        __half* dW = hsm + HBUF;
        #pragma unroll
        for (int l = 0; l < 4; l++) {
            int r = rr + l*32;
            cpa16(dX + r*HSTRIDE + q8*8, A + (size_t)r*CH + q8*8);
            cpa16(dW + r*HSTRIDE + q8*8, W + (size_t)r*CH + q8*8);
        }
        CPA_COMMIT(); CPA_WAIT0();
    }
    __syncthreads();

    int ao = wm*HSTRIDE + a_lane_off(lane);
    int bo = wn*HSTRIDE + b_lane_off(lane);

    #pragma unroll
    for (int kc = 0; kc < 2; kc++) {
        int buf = kc & 1;
        if (kc + 1 < 2) {
            __half* dX = hsm + (buf^1)*2*HBUF;
            __half* dW = dX + HBUF;
            #pragma unroll
            for (int l = 0; l < 4; l++) {
                int r = rr + l*32;
                cpa16(dX + r*HSTRIDE + q8*8, A + (size_t)r*CH + 64 + q8*8);
                cpa16(dW + r*HSTRIDE + q8*8, W + (size_t)r*CH + 64 + q8*8);
            }
            CPA_COMMIT();
        }
        const __half* cX = hsm + buf*2*HBUF;
        const __half* cW = cX + HBUF;
        #pragma unroll
        for (int ks = 0; ks < 4; ks++) {
            int kb = ks * 16;
            uint32_t af[4][4], bf[2][4];
            #pragma unroll
            for (int mt = 0; mt < 4; mt++) ldsm4(af[mt], cX + ao + mt*16*HSTRIDE + kb);
            #pragma unroll
            for (int np = 0; np < 2; np++) ldsm4(bf[np], cW + bo + np*16*HSTRIDE + kb);
            #pragma unroll
            for (int mt = 0; mt < 4; mt++)
                #pragma unroll
                for (int nt = 0; nt < 4; nt++)
                    mma16(acc[mt][nt], af[mt], &bf[nt>>1][(nt&1)*2]);
        }
        if (kc + 1 < 2) { CPA_WAIT0(); }
        __syncthreads();
    }

    float* a_s = (float*)hsm;        // [32][132] f32
    float* b_s = a_s + 32*132;
    int crow = lane >> 2, ccol = (lane & 3) * 2;
    #pragma unroll
    for (int mt = 0; mt < 4; mt++) {
        #pragma unroll
        for (int nt = 0; nt < 4; nt++) {
            float g0r1 = __shfl_xor_sync(0xffffffffu, acc[mt][nt][0], 1);
            float g1r1 = __shfl_xor_sync(0xffffffffu, acc[mt][nt][1], 1);
            float g0r2 = __shfl_xor_sync(0xffffffffu, acc[mt][nt][2], 1);
            float g1r2 = __shfl_xor_sync(0xffffffffu, acc[mt][nt][3], 1);
            if ((lane & 1) == 0) {
                int j  = wn + nt*8 + ccol;
                int cl = j >> 2;
                int r1 = wm + mt*16 + crow, r2 = r1 + 8;
                float mk1 = m_s[r1], mk2 = m_s[r2];
                a_s[cl*132 + r1] = acc[mt][nt][0] * mk1 * sigm(g0r1);
                b_s[cl*132 + r1] = acc[mt][nt][1] * mk1 * sigm(g1r1);
                a_s[cl*132 + r2] = acc[mt][nt][2] * mk2 * sigm(g0r2);
                b_s[cl*132 + r2] = acc[mt][nt][3] * mk2 * sigm(g1r2);
            }
        }
    }
    __syncthreads();
    int cb = cg * 32;
    #pragma unroll
    for (int it = 0; it < 2; it++) {
        int idx = tid + it*256;
        int ch = idx >> 4, f8 = idx & 15;
        float4 alo = *(float4*)(a_s + ch*132 + f8*8);
        float4 ahi = *(float4*)(a_s + ch*132 + f8*8 + 4);
        float4 blo = *(float4*)(b_s + ch*132 + f8*8);
        float4 bhi = *(float4*)(b_s + ch*132 + f8*8 + 4);
        *(uint4*)(ga + (size_t)(cb+ch)*RTOT + i0 + f8*8) = h8pack(alo, ahi);
        *(uint4*)(gb + (size_t)(cb+ch)*RTOT + i0 + f8*8) = h8pack(blo, bhi);
    }
}

// ---------------------------------------------------------------- fp16 mma einsum
// CTA tile 128x256, 8 warps as 2x4 of 64x64 warp tiles. 3-stage cp.async pipeline.
// smem stage: A 128x64 (HBUF) + B 256x64 (2*HBUF) = 55296 B; 3 stages = 165888 B.
#define KC 64
#define NCHUNK (NTOK/KC)           // 12
#define NSTAGE 3
#define ESTG (3*HBUF)              // halves per stage
#define DSMEM (NSTAGE*ESTG*2)      // 165888 B

__global__ void __launch_bounds__(256, 1) k_einsum_mma()
{
    extern __shared__ __half hsm[];
    int c  = blockIdx.z;
    int i0 = blockIdx.y * 128;
    int j0 = blockIdx.x * 256;
    const __half* ga = (const __half*)g_ab;
    const __half* gb = ga + (size_t)CH*RTOT;
    const __half* A = ga + (size_t)c*RTOT + (size_t)i0*NTOK;
    const __half* B = gb + (size_t)c*RTOT + (size_t)j0*NTOK;
    float*        O = g_o + (size_t)c*RTOT;

    int tid = threadIdx.x, lane = tid & 31, warp = tid >> 5;
    int wm = (warp >> 2) * 64;     // 0/64
    int wn = (warp & 3) * 64;      // 0/64/128/192

    float acc[4][8][4];
    #pragma unroll
    for (int mt = 0; mt < 4; mt++)
        #pragma unroll
        for (int nt = 0; nt < 8; nt++)
            #pragma unroll
            for (int e = 0; e < 4; e++) acc[mt][nt][e] = 0.f;

    int rr = tid >> 3, q = tid & 7;

    // prologue: issue chunks 0 and 1
    #pragma unroll
    for (int pc = 0; pc < 2; pc++) {
        __half* dA = hsm + pc*ESTG;
        __half* dB = dA + HBUF;
        const __half* As = A + pc*KC;
        const __half* Bs = B + pc*KC;
        #pragma unroll
        for (int l = 0; l < 4; l++) {
            int r = rr + l*32;
            cpa16(dA + r*HSTRIDE + q*8, As + (size_t)r*NTOK + q*8);
        }
        #pragma unroll
        for (int l = 0; l < 8; l++) {
            int r = rr + l*32;
            cpa16(dB + r*HSTRIDE + q*8, Bs + (size_t)r*NTOK + q*8);
        }
        CPA_COMMIT();
    }

    int ao = wm*HSTRIDE + a_lane_off(lane);
    int bo = wn*HSTRIDE + b_lane_off(lane);

    int buf = 0;
    for (int kc = 0; kc < NCHUNK; kc++) {
        CPA_WAIT1();
        __syncthreads();

        if (kc + 2 < NCHUNK) {
            int nb = buf + 2; if (nb >= NSTAGE) nb -= NSTAGE;
            __half* dA = hsm + nb*ESTG;
            __half* dB = dA + HBUF;
            const __half* As = A + (kc+2)*KC;
            const __half* Bs = B + (kc+2)*KC;
            #pragma unroll
            for (int l = 0; l < 4; l++) {
                int r = rr + l*32;
                cpa16(dA + r*HSTRIDE + q*8, As + (size_t)r*NTOK + q*8);
            }
            #pragma unroll
            for (int l = 0; l < 8; l++) {
                int r = rr + l*32;
                cpa16(dB + r*HSTRIDE + q*8, Bs + (size_t)r*NTOK + q*8);
            }
            CPA_COMMIT();
        }

        const __half* cA = hsm + buf*ESTG;
        const __half* cB = cA + HBUF;
        #pragma unroll
        for (int ks = 0; ks < 4; ks++) {
            int kb = ks * 16;
            uint32_t af[4][4], bf[4][4];
            #pragma unroll
            for (int mt = 0; mt < 4; mt++) ldsm4(af[mt], cA + ao + mt*16*HSTRIDE + kb);
            #pragma unroll
            for (int np = 0; np < 4; np++) ldsm4(bf[np], cB + bo + np*16*HSTRIDE + kb);
            #pragma unroll
            for (int mt = 0; mt < 4; mt++)
                #pragma unroll
                for (int nt = 0; nt < 8; nt++)
                    mma16(acc[mt][nt], af[mt], &bf[nt>>1][(nt&1)*2]);
        }
        buf++; if (buf >= NSTAGE) buf = 0;
    }

    int crow = lane >> 2, ccol = (lane & 3) * 2;
    #pragma unroll
    for (int mt = 0; mt < 4; mt++) {
        #pragma unroll
        for (int nt = 0; nt < 8; nt++) {
            float* d0 = O + (size_t)(i0 + wm + mt*16 + crow)*NTOK + j0 + wn + nt*8 + ccol;
            float2 v0; v0.x = acc[mt][nt][0]; v0.y = acc[mt][nt][1];
            float2 v1; v1.x = acc[mt][nt][2]; v1.y = acc[mt][nt][3];
            *(float2*)d0 = v0;
            *(float2*)(d0 + 8*NTOK) = v1;
        }
    }
}

// ---------------------------------------------------------------- LN2 + transpose (vectorized, fp16 out)
__global__ void k_ln2t(const float* __restrict__ w, const float* __restrict__ b)
{
    __shared__ float t[128*36];
    __shared__ float red[8][33];
    __shared__ float mu_s[32], rstd_s[32];
    __shared__ float w_s[128], b_s[128];
    int tid = threadIdx.x;
    size_t r0 = (size_t)blockIdx.x * 32;

    if (tid < 128) { w_s[tid] = w[tid]; b_s[tid] = b[tid]; }

    #pragma unroll
    for (int it = 0; it < 4; it++) {
        int idx = tid + it*256;
        int c = idx >> 3, rq = idx & 7;
        *(float4*)(t + c*36 + rq*4) = *(const float4*)(g_o + (size_t)c*RTOT + r0 + rq*4);
    }
    __syncthreads();

    int rr = tid & 31, part = tid >> 5;
    float s = 0.f;
    #pragma unroll
    for (int k = 0; k < 16; k++) s += t[(part*16 + k)*36 + rr];
    red[part][rr] = s;
    __syncthreads();
    if (tid < 32) {
        float tot = 0.f;
        #pragma unroll
        for (int p = 0; p < 8; p++) tot += red[p][tid];
        mu_s[tid] = tot * (1.f/128.f);
    }
    __syncthreads();
    float mu = mu_s[rr], qv = 0.f;
    #pragma unroll
    for (int k = 0; k < 16; k++) {
        float d = t[(part*16 + k)*36 + rr] - mu; qv += d*d;
    }
    __syncthreads();
    red[part][rr] = qv;
    __syncthreads();
    if (tid < 32) {
        float tot = 0.f;
        #pragma unroll
        for (int p = 0; p < 8; p++) tot += red[p][tid];
        rstd_s[tid] = rsqrtf(tot * (1.f/128.f) + 1e-5f);
    }
    __syncthreads();

    float rstd = rstd_s[rr];
    mu = mu_s[rr];
    __half* u = (__half*)g_ab;
    float f[16];
    #pragma unroll
    for (int k = 0; k < 16; k++) {
        int c = part*16 + k;
        f[k] = (t[c*36 + rr] - mu) * rstd * w_s[c] + b_s[c];
    }
    __half* dst = u + (r0 + rr)*CH + part*16;
    *(uint4*)(dst)     = h8pack(make_float4(f[0],f[1],f[2],f[3]),   make_float4(f[4],f[5],f[6],f[7]));
    *(uint4*)(dst + 8) = h8pack(make_float4(f[8],f[9],f[10],f[11]), make_float4(f[12],f[13],f[14],f[15]));
}

// ---------------------------------------------------------------- final (2 fused fp16 GEMMs, cp.async + ldmatrix)
#define FN_SMEM (8*HBUF*2)   // 147456 B

__global__ void __launch_bounds__(256, 1) k_final_mma(float* __restrict__ out)
{
    extern __shared__ __half hsm[];
    int tid = threadIdx.x, lane = tid & 31, warp = tid >> 5;
    size_t i0 = (size_t)blockIdx.x * 128;
    const __half* U = (const __half*)g_ab + i0 * CH;
    const __half* X = g_xh + i0 * CH;
    const __half* Wo = g_wh + (size_t)512*CH;
    const __half* Wg = g_wh + (size_t)640*CH;

    int wm = (warp >> 2) * 64;
    int wn = (warp & 3) * 32;

    float accU[4][4][4], accX[4][4][4];
    #pragma unroll
    for (int mt = 0; mt < 4; mt++)
        #pragma unroll
        for (int nt = 0; nt < 4; nt++)
            #pragma unroll
            for (int e = 0; e < 4; e++) { accU[mt][nt][e] = 0.f; accX[mt][nt][e] = 0.f; }

    int rr = tid >> 3, q8 = tid & 7;

    {
        __half* d0 = hsm;
        #pragma unroll
        for (int l = 0; l < 4; l++) {
            int r = rr + l*32;
            cpa16(d0 + 0*HBUF + r*HSTRIDE + q8*8, U  + (size_t)r*CH + q8*8);
            cpa16(d0 + 1*HBUF + r*HSTRIDE + q8*8, X  + (size_t)r*CH + q8*8);
            cpa16(d0 + 2*HBUF + r*HSTRIDE + q8*8, Wo + (size_t)r*CH + q8*8);
            cpa16(d0 + 3*HBUF + r*HSTRIDE + q8*8, Wg + (size_t)r*CH + q8*8);
        }
        CPA_COMMIT(); CPA_WAIT0();
    }
    __syncthreads();

    int ao = wm*HSTRIDE + a_lane_off(lane);
    int bo = wn*HSTRIDE + b_lane_off(lane);

    #pragma unroll
    for (int kc = 0; kc < 2; kc++) {
        int buf = kc & 1;
        if (kc + 1 < 2) {
            __half* d0 = hsm + (buf^1)*4*HBUF;
            #pragma unroll
            for (int l = 0; l < 4; l++) {
                int r = rr + l*32;
                cpa16(d0 + 0*HBUF + r*HSTRIDE + q8*8, U  + (size_t)r*CH + 64 + q8*8);
                cpa16(d0 + 1*HBUF + r*HSTRIDE + q8*8, X  + (size_t)r*CH + 64 + q8*8);
                cpa16(d0 + 2*HBUF + r*HSTRIDE + q8*8, Wo + (size_t)r*CH + 64 + q8*8);
                cpa16(d0 + 3*HBUF + r*HSTRIDE + q8*8, Wg + (size_t)r*CH + 64 + q8*8);
            }
            CPA_COMMIT();
        }
        const __half* cb = hsm + buf*4*HBUF;
        #pragma unroll
        for (int ks = 0; ks < 4; ks++) {
            int kb = ks * 16;
            uint32_t au[4][4], ax[4][4], bo2[2][4], bg2[2][4];
            #pragma unroll
            for (int mt = 0; mt < 4; mt++) {
                ldsm4(au[mt], cb + 0*HBUF + ao + mt*16*HSTRIDE + kb);
                ldsm4(ax[mt], cb + 1*HBUF + ao + mt*16*HSTRIDE + kb);
            }
            #pragma unroll
            for (int np = 0; np < 2; np++) {
                ldsm4(bo2[np], cb + 2*HBUF + bo + np*16*HSTRIDE + kb);
                ldsm4(bg2[np], cb + 3*HBUF + bo + np*16*HSTRIDE + kb);
            }
            #pragma unroll
            for (int mt = 0; mt < 4; mt++)
                #pragma unroll
                for (int nt = 0; nt < 4; nt++) {
                    mma16(accU[mt][nt], au[mt], &bo2[nt>>1][(nt&1)*2]);
                    mma16(accX[mt][nt], ax[mt], &bg2[nt>>1][(nt&1)*2]);
                }
        }
        if (kc + 1 < 2) { CPA_WAIT0(); }
        __syncthreads();
    }

    int crow = lane >> 2, ccol = (lane & 3) * 2;
    #pragma unroll
    for (int mt = 0; mt < 4; mt++) {
        #pragma unroll
        for (int nt = 0; nt < 4; nt++) {
            size_t r1 = i0 + wm + mt*16 + crow;
            int col = wn + nt*8 + ccol;
            float2 v0, v1;
            v0.x = accU[mt][nt][0] * sigm(accX[mt][nt][0]);
            v0.y = accU[mt][nt][1] * sigm(accX[mt][nt][1]);
            v1.x = accU[mt][nt][2] * sigm(accX[mt][nt][2]);
            v1.y = accU[mt][nt][3] * sigm(accX[mt][nt][3]);
            *(float2*)(out + r1*CH + col) = v0;
            *(float2*)(out + (r1+8)*CH + col) = v1;
        }
    }
}

// ---------------------------------------------------------------- launch
extern "C" void kernel_launch(void* const* d_in, const int* in_sizes, int n_in,
                              void* d_out, int out_size)
{
    const float* pair     = (const float*)d_in[0];
    const float* mask     = (const float*)d_in[1];
    const float* ln1_w    = (const float*)d_in[2];
    const float* ln1_b    = (const float*)d_in[3];
    const float* proj_w   = (const float*)d_in[4];
    const float* gate_w   = (const float*)d_in[5];
    const float* ln2_w    = (const float*)d_in[6];
    const float* ln2_b    = (const float*)d_in[7];
    const float* out_w    = (const float*)d_in[8];
    const float* gating_w = (const float*)d_in[9];
    float* out = (float*)d_out;

    cudaFuncSetAttribute(k_projgate_mma, cudaFuncAttributeMaxDynamicSharedMemorySize, PG_SMEM);
    cudaFuncSetAttribute(k_einsum_mma,   cudaFuncAttributeMaxDynamicSharedMemorySize, DSMEM);
    cudaFuncSetAttribute(k_final_mma,    cudaFuncAttributeMaxDynamicSharedMemorySize, FN_SMEM);

    k_cvtw<<<48, 256>>>(proj_w, gate_w, out_w, gating_w);
    k_ln1<<<RTOT/8, 256>>>(pair, ln1_w, ln1_b);
    k_projgate_mma<<<dim3(4, RTOT/128), 256, PG_SMEM>>>(mask);
    k_einsum_mma<<<dim3(NTOK/256, NTOK/128, CH), 256, DSMEM>>>();
    k_ln2t<<<RTOT/32, 256>>>(ln2_w, ln2_b);
    k_final_mma<<<RTOT/128, 256, FN_SMEM>>>(out);
}

// round 15
// speedup vs baseline: 1.0230x; 1.0230x over previous
#include <cuda_runtime.h>
#include <cuda_fp16.h>
#include <math.h>
#include <stdint.h>

// TriangleMultiplication: N=768, C=128 — fp16 tensor-core pipeline + cp.async + ldmatrix
//   k_cvtw         : weights -> fp16
//   k_ln1          : x = LN(pair)                            -> g_xh [r][c] fp16
//   k_projgate_mma : a,b = split((x@Wp^T)*mask*sig(x@Wg^T))  -> ga,gb [c][r] fp16
//   k_einsum_mma   : out_c = A_c @ B_c^T per channel (fp16, 3-stage) -> g_oh [c][i][j] fp16
//   k_ln2t         : u = LN_c(out) transposed                -> u (= g_ab reuse) fp16 [r][c]
//   k_final_mma    : out = (u@Wo^T) * sig(x@Wgat^T) (fp16)   -> d_out f32

#define NTOK 768
#define CH   128
#define RTOT (NTOK*NTOK)   // 589824

__device__ __half g_xh[(size_t)RTOT*CH];
__device__ __half g_oh[(size_t)CH*RTOT];
__device__ __align__(256) unsigned char g_ab[(size_t)CH*RTOT*4];
__device__ __half g_wh[768*CH];

__device__ __forceinline__ float sigm(float v){ return 1.f/(1.f+expf(-v)); }

__device__ __forceinline__ void mma16(float* d, const uint32_t* a, const uint32_t* b){
    asm volatile(
        "mma.sync.aligned.m16n8k16.row.col.f32.f16.f16.f32 "
        "{%0,%1,%2,%3}, {%4,%5,%6,%7}, {%8,%9}, {%0,%1,%2,%3};"
        : "+f"(d[0]), "+f"(d[1]), "+f"(d[2]), "+f"(d[3])
        : "r"(a[0]), "r"(a[1]), "r"(a[2]), "r"(a[3]), "r"(b[0]), "r"(b[1]));
}

__device__ __forceinline__ void ldsm4(uint32_t* r, const __half* p){
    uint32_t a;
    asm("{ .reg .u64 t; cvta.to.shared.u64 t, %1; cvt.u32.u64 %0, t; }" : "=r"(a) : "l"(p));
    asm volatile("ldmatrix.sync.aligned.m8n8.x4.shared.b16 {%0,%1,%2,%3}, [%4];"
        : "=r"(r[0]), "=r"(r[1]), "=r"(r[2]), "=r"(r[3]) : "r"(a));
}

__device__ __forceinline__ uint32_t h2pack(float a, float b){
    __half2 h = __floats2half2_rn(a, b);
    return *(uint32_t*)&h;
}
__device__ __forceinline__ uint4 h8pack(float4 lo, float4 hi){
    uint4 r;
    r.x = h2pack(lo.x, lo.y);
    r.y = h2pack(lo.z, lo.w);
    r.z = h2pack(hi.x, hi.y);
    r.w = h2pack(hi.z, hi.w);
    return r;
}
__device__ __forceinline__ uint2 h4pack(float4 v){
    uint2 r;
    r.x = h2pack(v.x, v.y);
    r.y = h2pack(v.z, v.w);
    return r;
}

__device__ __forceinline__ void cpa16(__half* dst, const __half* src){
    uint32_t s;
    asm("{ .reg .u64 t; cvta.to.shared.u64 t, %1; cvt.u32.u64 %0, t; }" : "=r"(s) : "l"(dst));
    asm volatile("cp.async.cg.shared.global [%0], [%1], 16;" :: "r"(s), "l"(src));
}
#define CPA_COMMIT() asm volatile("cp.async.commit_group;" ::: "memory")
#define CPA_WAIT0()  asm volatile("cp.async.wait_group 0;" ::: "memory")
#define CPA_WAIT1()  asm volatile("cp.async.wait_group 1;" ::: "memory")

#define HSTRIDE 72
#define HBUF (128*HSTRIDE)

__device__ __forceinline__ int a_lane_off(int lane){
    return ((lane & 7) + ((lane >> 3) & 1) * 8) * HSTRIDE + (lane >> 4) * 8;
}
__device__ __forceinline__ int b_lane_off(int lane){
    return ((lane & 7) + (lane >> 4) * 8) * HSTRIDE + ((lane >> 3) & 1) * 8;
}

// ---------------------------------------------------------------- weight convert
__global__ void k_cvtw(const float* __restrict__ projw, const float* __restrict__ gatew,
                       const float* __restrict__ outw,  const float* __restrict__ gatingw)
{
    int idx = blockIdx.x*256 + threadIdx.x;
    int row = idx >> 4, q8 = idx & 15;
    const float* src;
    if (row < 512) {
        int c = row >> 2, q = row & 3;
        src = (q < 2) ? projw + (size_t)(2*c+q)*CH : gatew + (size_t)(2*c+q-2)*CH;
    } else if (row < 640) {
        src = outw + (size_t)(row-512)*CH;
    } else {
        src = gatingw + (size_t)(row-640)*CH;
    }
    float4 lo = *(const float4*)(src + q8*8);
    float4 hi = *(const float4*)(src + q8*8 + 4);
    *(uint4*)(g_wh + (size_t)row*CH + q8*8) = h8pack(lo, hi);
}

// ---------------------------------------------------------------- LN1 -> fp16 x
__global__ void k_ln1(const float* __restrict__ pair,
                      const float* __restrict__ w,
                      const float* __restrict__ b)
{
    int warp = threadIdx.x >> 5, lane = threadIdx.x & 31;
    size_t r = (size_t)blockIdx.x * 8 + warp;
    const float4* src = (const float4*)(pair + r * CH);
    float4 v = src[lane];
    float s = v.x + v.y + v.z + v.w;
    #pragma unroll
    for (int o = 16; o; o >>= 1) s += __shfl_xor_sync(0xffffffffu, s, o);
    float mu = s * (1.f/128.f);
    float dx = v.x-mu, dy = v.y-mu, dz = v.z-mu, dw = v.w-mu;
    float q = dx*dx + dy*dy + dz*dz + dw*dw;
    #pragma unroll
    for (int o = 16; o; o >>= 1) q += __shfl_xor_sync(0xffffffffu, q, o);
    float rstd = rsqrtf(q * (1.f/128.f) + 1e-5f);
    float4 wv = ((const float4*)w)[lane];
    float4 bv = ((const float4*)b)[lane];
    float4 o4;
    o4.x = dx*rstd*wv.x + bv.x;
    o4.y = dy*rstd*wv.y + bv.y;
    o4.z = dz*rstd*wv.z + bv.z;
    o4.w = dw*rstd*wv.w + bv.w;
    *(uint2*)(g_xh + r * CH + lane*4) = h4pack(o4);
}

// ---------------------------------------------------------------- proj+gate (fp16 mma + cp.async + ldmatrix)
#define PG_SMEM (4*HBUF*2)   // 73728 B

__global__ void __launch_bounds__(256, 2) k_projgate_mma(const float* __restrict__ mask)
{
    extern __shared__ __half hsm[];
    __shared__ float m_s[128];
    int tid = threadIdx.x, lane = tid & 31, warp = tid >> 5;
    int cg = blockIdx.x;
    size_t i0 = (size_t)blockIdx.y * 128;
    const __half* A = g_xh + i0 * CH;
    __half* ga = (__half*)g_ab;
    __half* gb = ga + (size_t)CH*RTOT;

    if (tid < 128) m_s[tid] = mask[(int)(i0 % NTOK) + tid];

    int wm = (warp >> 2) * 64;
    int wn = (warp & 3) * 32;

    float acc[4][4][4];
    #pragma unroll
    for (int mt = 0; mt < 4; mt++)
        #pragma unroll
        for (int nt = 0; nt < 4; nt++)
            #pragma unroll
            for (int e = 0; e < 4; e++) acc[mt][nt][e] = 0.f;

    int rr = tid >> 3, q8 = tid & 7;
    const __half* W = g_wh + (size_t)(cg*128) * CH;

    {
        __half* dX = hsm;
        __half* dW = hsm + HBUF;
        #pragma unroll
        for (int l = 0; l < 4; l++) {
            int r = rr + l*32;
            cpa16(dX + r*HSTRIDE + q8*8, A + (size_t)r*CH + q8*8);
            cpa16(dW + r*HSTRIDE + q8*8, W + (size_t)r*CH + q8*8);
        }
        CPA_COMMIT(); CPA_WAIT0();
    }
    __syncthreads();

    int ao = wm*HSTRIDE + a_lane_off(lane);
    int bo = wn*HSTRIDE + b_lane_off(lane);

    #pragma unroll
    for (int kc = 0; kc < 2; kc++) {
        int buf = kc & 1;
        if (kc + 1 < 2) {
            __half* dX = hsm + (buf^1)*2*HBUF;
            __half* dW = dX + HBUF;
            #pragma unroll
            for (int l = 0; l < 4; l++) {
                int r = rr + l*32;
                cpa16(dX + r*HSTRIDE + q8*8, A + (size_t)r*CH + 64 + q8*8);
                cpa16(dW + r*HSTRIDE + q8*8, W + (size_t)r*CH + 64 + q8*8);
            }
            CPA_COMMIT();
        }
        const __half* cX = hsm + buf*2*HBUF;
        const __half* cW = cX + HBUF;
        #pragma unroll
        for (int ks = 0; ks < 4; ks++) {
            int kb = ks * 16;
            uint32_t af[4][4], bf[2][4];
            #pragma unroll
            for (int mt = 0; mt < 4; mt++) ldsm4(af[mt], cX + ao + mt*16*HSTRIDE + kb);
            #pragma unroll
            for (int np = 0; np < 2; np++) ldsm4(bf[np], cW + bo + np*16*HSTRIDE + kb);
            #pragma unroll
            for (int mt = 0; mt < 4; mt++)
                #pragma unroll
                for (int nt = 0; nt < 4; nt++)
                    mma16(acc[mt][nt], af[mt], &bf[nt>>1][(nt&1)*2]);
        }
        if (kc + 1 < 2) { CPA_WAIT0(); }
        __syncthreads();
    }

    float* a_s = (float*)hsm;        // [32][132] f32
    float* b_s = a_s + 32*132;
    int crow = lane >> 2, ccol = (lane & 3) * 2;
    #pragma unroll
    for (int mt = 0; mt < 4; mt++) {
        #pragma unroll
        for (int nt = 0; nt < 4; nt++) {
            float g0r1 = __shfl_xor_sync(0xffffffffu, acc[mt][nt][0], 1);
            float g1r1 = __shfl_xor_sync(0xffffffffu, acc[mt][nt][1], 1);
            float g0r2 = __shfl_xor_sync(0xffffffffu, acc[mt][nt][2], 1);
            float g1r2 = __shfl_xor_sync(0xffffffffu, acc[mt][nt][3], 1);
            if ((lane & 1) == 0) {
                int j  = wn + nt*8 + ccol;
                int cl = j >> 2;
                int r1 = wm + mt*16 + crow, r2 = r1 + 8;
                float mk1 = m_s[r1], mk2 = m_s[r2];
                a_s[cl*132 + r1] = acc[mt][nt][0] * mk1 * sigm(g0r1);
                b_s[cl*132 + r1] = acc[mt][nt][1] * mk1 * sigm(g1r1);
                a_s[cl*132 + r2] = acc[mt][nt][2] * mk2 * sigm(g0r2);
                b_s[cl*132 + r2] = acc[mt][nt][3] * mk2 * sigm(g1r2);
            }
        }
    }
    __syncthreads();
    int cb = cg * 32;
    #pragma unroll
    for (int it = 0; it < 2; it++) {
        int idx = tid + it*256;
        int ch = idx >> 4, f8 = idx & 15;
        float4 alo = *(float4*)(a_s + ch*132 + f8*8);
        float4 ahi = *(float4*)(a_s + ch*132 + f8*8 + 4);
        float4 blo = *(float4*)(b_s + ch*132 + f8*8);
        float4 bhi = *(float4*)(b_s + ch*132 + f8*8 + 4);
        *(uint4*)(ga + (size_t)(cb+ch)*RTOT + i0 + f8*8) = h8pack(alo, ahi);
        *(uint4*)(gb + (size_t)(cb+ch)*RTOT + i0 + f8*8) = h8pack(blo, bhi);
    }
}

// ---------------------------------------------------------------- fp16 mma einsum (3-stage, 128x128 tile) -> fp16 out
#define KC 64
#define NCHUNK (NTOK/KC)           // 12
#define NSTAGE 3
#define DSMEM (NSTAGE*2*HBUF*2)    // 110592 B

__global__ void __launch_bounds__(256, 2) k_einsum_mma()
{
    extern __shared__ __half hsm[];
    int c  = blockIdx.z;
    int i0 = blockIdx.y * 128;
    int j0 = blockIdx.x * 128;
    const __half* ga = (const __half*)g_ab;
    const __half* gb = ga + (size_t)CH*RTOT;
    const __half* A = ga + (size_t)c*RTOT + (size_t)i0*NTOK;
    const __half* B = gb + (size_t)c*RTOT + (size_t)j0*NTOK;
    __half*       O = g_oh + (size_t)c*RTOT;

    int tid = threadIdx.x, lane = tid & 31, warp = tid >> 5;
    int wm = (warp >> 2) * 64;
    int wn = (warp & 3) * 32;

    float acc[4][4][4];
    #pragma unroll
    for (int mt = 0; mt < 4; mt++)
        #pragma unroll
        for (int nt = 0; nt < 4; nt++)
            #pragma unroll
            for (int e = 0; e < 4; e++) acc[mt][nt][e] = 0.f;

    int rr = tid >> 3, q = tid & 7;

    #pragma unroll
    for (int pc = 0; pc < 2; pc++) {
        __half* dA = hsm + pc*2*HBUF;
        __half* dB = dA + HBUF;
        const __half* As = A + pc*KC;
        const __half* Bs = B + pc*KC;
        #pragma unroll
        for (int l = 0; l < 4; l++) {
            int r = rr + l*32;
            cpa16(dA + r*HSTRIDE + q*8, As + (size_t)r*NTOK + q*8);
            cpa16(dB + r*HSTRIDE + q*8, Bs + (size_t)r*NTOK + q*8);
        }
        CPA_COMMIT();
    }

    int ao = wm*HSTRIDE + a_lane_off(lane);
    int bo = wn*HSTRIDE + b_lane_off(lane);

    int buf = 0;
    for (int kc = 0; kc < NCHUNK; kc++) {
        CPA_WAIT1();
        __syncthreads();

        if (kc + 2 < NCHUNK) {
            int nb = buf + 2; if (nb >= NSTAGE) nb -= NSTAGE;
            __half* dA = hsm + nb*2*HBUF;
            __half* dB = dA + HBUF;
            const __half* As = A + (kc+2)*KC;
            const __half* Bs = B + (kc+2)*KC;
            #pragma unroll
            for (int l = 0; l < 4; l++) {
                int r = rr + l*32;
                cpa16(dA + r*HSTRIDE + q*8, As + (size_t)r*NTOK + q*8);
                cpa16(dB + r*HSTRIDE + q*8, Bs + (size_t)r*NTOK + q*8);
            }
            CPA_COMMIT();
        }

        const __half* cA = hsm + buf*2*HBUF;
        const __half* cB = cA + HBUF;
        #pragma unroll
        for (int ks = 0; ks < 4; ks++) {
            int kb = ks * 16;
            uint32_t af[4][4], bf[2][4];
            #pragma unroll
            for (int mt = 0; mt < 4; mt++) ldsm4(af[mt], cA + ao + mt*16*HSTRIDE + kb);
            #pragma unroll
            for (int np = 0; np < 2; np++) ldsm4(bf[np], cB + bo + np*16*HSTRIDE + kb);
            #pragma unroll
            for (int mt = 0; mt < 4; mt++)
                #pragma unroll
                for (int nt = 0; nt < 4; nt++)
                    mma16(acc[mt][nt], af[mt], &bf[nt>>1][(nt&1)*2]);
        }
        buf++; if (buf >= NSTAGE) buf = 0;
    }

    // epilogue: fp16 output (2 halves per u32 store)
    int crow = lane >> 2, ccol = (lane & 3) * 2;
    #pragma unroll
    for (int mt = 0; mt < 4; mt++) {
        #pragma unroll
        for (int nt = 0; nt < 4; nt++) {
            __half* d0 = O + (size_t)(i0 + wm + mt*16 + crow)*NTOK + j0 + wn + nt*8 + ccol;
            *(uint32_t*)d0 = h2pack(acc[mt][nt][0], acc[mt][nt][1]);
            *(uint32_t*)(d0 + 8*NTOK) = h2pack(acc[mt][nt][2], acc[mt][nt][3]);
        }
    }
}

// ---------------------------------------------------------------- LN2 + transpose (fp16 in, fp16 out)
__global__ void k_ln2t(const float* __restrict__ w, const float* __restrict__ b)
{
    __shared__ float t[128*36];
    __shared__ float red[8][33];
    __shared__ float mu_s[32], rstd_s[32];
    __shared__ float w_s[128], b_s[128];
    int tid = threadIdx.x;
    size_t r0 = (size_t)blockIdx.x * 32;

    if (tid < 128) { w_s[tid] = w[tid]; b_s[tid] = b[tid]; }

    #pragma unroll
    for (int it = 0; it < 2; it++) {
        int idx = tid + it*256;            // 0..511 : c(0..127) x rq(0..3), 8 halves each
        int c = idx >> 2, rq = idx & 3;
        uint4 v = *(const uint4*)(g_oh + (size_t)c*RTOT + r0 + rq*8);
        float* dst = t + c*36 + rq*8;
        float2 f0 = __half22float2(*(__half2*)&v.x);
        float2 f1 = __half22float2(*(__half2*)&v.y);
        float2 f2 = __half22float2(*(__half2*)&v.z);
        float2 f3 = __half22float2(*(__half2*)&v.w);
        dst[0] = f0.x; dst[1] = f0.y;
        dst[2] = f1.x; dst[3] = f1.y;
        dst[4] = f2.x; dst[5] = f2.y;
        dst[6] = f3.x; dst[7] = f3.y;
    }
    __syncthreads();

    int rr = tid & 31, part = tid >> 5;
    float s = 0.f;
    #pragma unroll
    for (int k = 0; k < 16; k++) s += t[(part*16 + k)*36 + rr];
    red[part][rr] = s;
    __syncthreads();
    if (tid < 32) {
        float tot = 0.f;
        #pragma unroll
        for (int p = 0; p < 8; p++) tot += red[p][tid];
        mu_s[tid] = tot * (1.f/128.f);
    }
    __syncthreads();
    float mu = mu_s[rr], qv = 0.f;
    #pragma unroll
    for (int k = 0; k < 16; k++) {
        float d = t[(part*16 + k)*36 + rr] - mu; qv += d*d;
    }
    __syncthreads();
    red[part][rr] = qv;
    __syncthreads();
    if (tid < 32) {
        float tot = 0.f;
        #pragma unroll
        for (int p = 0; p < 8; p++) tot += red[p][tid];
        rstd_s[tid] = rsqrtf(tot * (1.f/128.f) + 1e-5f);
    }
    __syncthreads();

    float rstd = rstd_s[rr];
    mu = mu_s[rr];
    __half* u = (__half*)g_ab;   // ga/gb dead: reuse as fp16 u buffer [r][c]
    float f[16];
    #pragma unroll
    for (int k = 0; k < 16; k++) {
        int c = part*16 + k;
        f[k] = (t[c*36 + rr] - mu) * rstd * w_s[c] + b_s[c];
    }
    __half* dst = u + (r0 + rr)*CH + part*16;
    *(uint4*)(dst)     = h8pack(make_float4(f[0],f[1],f[2],f[3]),   make_float4(f[4],f[5],f[6],f[7]));
    *(uint4*)(dst + 8) = h8pack(make_float4(f[8],f[9],f[10],f[11]), make_float4(f[12],f[13],f[14],f[15]));
}

// ---------------------------------------------------------------- final (2 fused fp16 GEMMs, cp.async + ldmatrix)
#define FN_SMEM (8*HBUF*2)   // 147456 B

__global__ void __launch_bounds__(256, 1) k_final_mma(float* __restrict__ out)
{
    extern __shared__ __half hsm[];
    int tid = threadIdx.x, lane = tid & 31, warp = tid >> 5;
    size_t i0 = (size_t)blockIdx.x * 128;
    const __half* U = (const __half*)g_ab + i0 * CH;
    const __half* X = g_xh + i0 * CH;
    const __half* Wo = g_wh + (size_t)512*CH;
    const __half* Wg = g_wh + (size_t)640*CH;

    int wm = (warp >> 2) * 64;
    int wn = (warp & 3) * 32;

    float accU[4][4][4], accX[4][4][4];
    #pragma unroll
    for (int mt = 0; mt < 4; mt++)
        #pragma unroll
        for (int nt = 0; nt < 4; nt++)
            #pragma unroll
            for (int e = 0; e < 4; e++) { accU[mt][nt][e] = 0.f; accX[mt][nt][e] = 0.f; }

    int rr = tid >> 3, q8 = tid & 7;

    {
        __half* d0 = hsm;
        #pragma unroll
        for (int l = 0; l < 4; l++) {
            int r = rr + l*32;
            cpa16(d0 + 0*HBUF + r*HSTRIDE + q8*8, U  + (size_t)r*CH + q8*8);
            cpa16(d0 + 1*HBUF + r*HSTRIDE + q8*8, X  + (size_t)r*CH + q8*8);
            cpa16(d0 + 2*HBUF + r*HSTRIDE + q8*8, Wo + (size_t)r*CH + q8*8);
            cpa16(d0 + 3*HBUF + r*HSTRIDE + q8*8, Wg + (size_t)r*CH + q8*8);
        }
        CPA_COMMIT(); CPA_WAIT0();
    }
    __syncthreads();

    int ao = wm*HSTRIDE + a_lane_off(lane);
    int bo = wn*HSTRIDE + b_lane_off(lane);

    #pragma unroll
    for (int kc = 0; kc < 2; kc++) {
        int buf = kc & 1;
        if (kc + 1 < 2) {
            __half* d0 = hsm + (buf^1)*4*HBUF;
            #pragma unroll
            for (int l = 0; l < 4; l++) {
                int r = rr + l*32;
                cpa16(d0 + 0*HBUF + r*HSTRIDE + q8*8, U  + (size_t)r*CH + 64 + q8*8);
                cpa16(d0 + 1*HBUF + r*HSTRIDE + q8*8, X  + (size_t)r*CH + 64 + q8*8);
                cpa16(d0 + 2*HBUF + r*HSTRIDE + q8*8, Wo + (size_t)r*CH + 64 + q8*8);
                cpa16(d0 + 3*HBUF + r*HSTRIDE + q8*8, Wg + (size_t)r*CH + 64 + q8*8);
            }
            CPA_COMMIT();
        }
        const __half* cb = hsm + buf*4*HBUF;
        #pragma unroll
        for (int ks = 0; ks < 4; ks++) {
            int kb = ks * 16;
            uint32_t au[4][4], ax[4][4], bo2[2][4], bg2[2][4];
            #pragma unroll
            for (int mt = 0; mt < 4; mt++) {
                ldsm4(au[mt], cb + 0*HBUF + ao + mt*16*HSTRIDE + kb);
                ldsm4(ax[mt], cb + 1*HBUF + ao + mt*16*HSTRIDE + kb);
            }
            #pragma unroll
            for (int np = 0; np < 2; np++) {
                ldsm4(bo2[np], cb + 2*HBUF + bo + np*16*HSTRIDE + kb);
                ldsm4(bg2[np], cb + 3*HBUF + bo + np*16*HSTRIDE + kb);
            }
            #pragma unroll
            for (int mt = 0; mt < 4; mt++)
                #pragma unroll
                for (int nt = 0; nt < 4; nt++) {
                    mma16(accU[mt][nt], au[mt], &bo2[nt>>1][(nt&1)*2]);
                    mma16(accX[mt][nt], ax[mt], &bg2[nt>>1][(nt&1)*2]);
                }
        }
        if (kc + 1 < 2) { CPA_WAIT0(); }
        __syncthreads();
    }

    int crow = lane >> 2, ccol = (lane & 3) * 2;
    #pragma unroll
    for (int mt = 0; mt < 4; mt++) {
        #pragma unroll
        for (int nt = 0; nt < 4; nt++) {
            size_t r1 = i0 + wm + mt*16 + crow;
            int col = wn + nt*8 + ccol;
            float2 v0, v1;
            v0.x = accU[mt][nt][0] * sigm(accX[mt][nt][0]);
            v0.y = accU[mt][nt][1] * sigm(accX[mt][nt][1]);
            v1.x = accU[mt][nt][2] * sigm(accX[mt][nt][2]);
            v1.y = accU[mt][nt][3] * sigm(accX[mt][nt][3]);
            *(float2*)(out + r1*CH + col) = v0;
            *(float2*)(out + (r1+8)*CH + col) = v1;
        }
    }
}

// ---------------------------------------------------------------- launch
extern "C" void kernel_launch(void* const* d_in, const int* in_sizes, int n_in,
                              void* d_out, int out_size)
{
    const float* pair     = (const float*)d_in[0];
    const float* mask     = (const float*)d_in[1];
    const float* ln1_w    = (const float*)d_in[2];
    const float* ln1_b    = (const float*)d_in[3];
    const float* proj_w   = (const float*)d_in[4];
    const float* gate_w   = (const float*)d_in[5];
    const float* ln2_w    = (const float*)d_in[6];
    const float* ln2_b    = (const float*)d_in[7];
    const float* out_w    = (const float*)d_in[8];
    const float* gating_w = (const float*)d_in[9];
    float* out = (float*)d_out;

    cudaFuncSetAttribute(k_projgate_mma, cudaFuncAttributeMaxDynamicSharedMemorySize, PG_SMEM);
    cudaFuncSetAttribute(k_einsum_mma,   cudaFuncAttributeMaxDynamicSharedMemorySize, DSMEM);
    cudaFuncSetAttribute(k_final_mma,    cudaFuncAttributeMaxDynamicSharedMemorySize, FN_SMEM);

    k_cvtw<<<48, 256>>>(proj_w, gate_w, out_w, gating_w);
    k_ln1<<<RTOT/8, 256>>>(pair, ln1_w, ln1_b);
    k_projgate_mma<<<dim3(4, RTOT/128), 256, PG_SMEM>>>(mask);
    k_einsum_mma<<<dim3(NTOK/128, NTOK/128, CH), 256, DSMEM>>>();
    k_ln2t<<<RTOT/32, 256>>>(ln2_w, ln2_b);
    k_final_mma<<<RTOT/128, 256, FN_SMEM>>>(out);
}

// round 16
// speedup vs baseline: 1.0714x; 1.0474x over previous
#include <cuda_runtime.h>
#include <cuda_fp16.h>
#include <math.h>
#include <stdint.h>

// TriangleMultiplication: N=768, C=128 — fp16 tensor-core pipeline + cp.async + ldmatrix
//   k_cvtw         : weights -> fp16
//   k_ln1          : x = LN(pair)                            -> g_xh [r][c] fp16
//   k_projgate_mma : streaming row-blocks, resident W        -> ga,gb [c][r] fp16
//   k_einsum_mma   : out_c = A_c @ B_c^T per channel (fp16, 3-stage) -> g_oh [c][i][j] fp16
//   k_ln2t         : u = LN_c(out) transposed                -> u (= g_ab reuse) fp16 [r][c]
//   k_final_mma    : streaming row-blocks, resident Wo/Wg    -> d_out f32

#define NTOK 768
#define CH   128
#define RTOT (NTOK*NTOK)   // 589824

__device__ __half g_xh[(size_t)RTOT*CH];
__device__ __half g_oh[(size_t)CH*RTOT];
__device__ __align__(256) unsigned char g_ab[(size_t)CH*RTOT*4];
__device__ __half g_wh[768*CH];   // [0,512)=proj/gate interleaved, [512,640)=out_w, [640,768)=gating_w

__device__ __forceinline__ float sigm(float v){ return 1.f/(1.f+expf(-v)); }

__device__ __forceinline__ void mma16(float* d, const uint32_t* a, const uint32_t* b){
    asm volatile(
        "mma.sync.aligned.m16n8k16.row.col.f32.f16.f16.f32 "
        "{%0,%1,%2,%3}, {%4,%5,%6,%7}, {%8,%9}, {%0,%1,%2,%3};"
        : "+f"(d[0]), "+f"(d[1]), "+f"(d[2]), "+f"(d[3])
        : "r"(a[0]), "r"(a[1]), "r"(a[2]), "r"(a[3]), "r"(b[0]), "r"(b[1]));
}

__device__ __forceinline__ void ldsm4(uint32_t* r, const __half* p){
    uint32_t a;
    asm("{ .reg .u64 t; cvta.to.shared.u64 t, %1; cvt.u32.u64 %0, t; }" : "=r"(a) : "l"(p));
    asm volatile("ldmatrix.sync.aligned.m8n8.x4.shared.b16 {%0,%1,%2,%3}, [%4];"
        : "=r"(r[0]), "=r"(r[1]), "=r"(r[2]), "=r"(r[3]) : "r"(a));
}

__device__ __forceinline__ uint32_t h2pack(float a, float b){
    __half2 h = __floats2half2_rn(a, b);
    return *(uint32_t*)&h;
}
__device__ __forceinline__ uint4 h8pack(float4 lo, float4 hi){
    uint4 r;
    r.x = h2pack(lo.x, lo.y);
    r.y = h2pack(lo.z, lo.w);
    r.z = h2pack(hi.x, hi.y);
    r.w = h2pack(hi.z, hi.w);
    return r;
}
__device__ __forceinline__ uint2 h4pack(float4 v){
    uint2 r;
    r.x = h2pack(v.x, v.y);
    r.y = h2pack(v.z, v.w);
    return r;
}

__device__ __forceinline__ void cpa16(__half* dst, const __half* src){
    uint32_t s;
    asm("{ .reg .u64 t; cvta.to.shared.u64 t, %1; cvt.u32.u64 %0, t; }" : "=r"(s) : "l"(dst));
    asm volatile("cp.async.cg.shared.global [%0], [%1], 16;" :: "r"(s), "l"(src));
}
#define CPA_COMMIT() asm volatile("cp.async.commit_group;" ::: "memory")
#define CPA_WAIT0()  asm volatile("cp.async.wait_group 0;" ::: "memory")
#define CPA_WAIT1()  asm volatile("cp.async.wait_group 1;" ::: "memory")

#define HSTRIDE 72
#define HBUF (128*HSTRIDE)    // halves per 128x64 tile

__device__ __forceinline__ int a_lane_off(int lane){
    return ((lane & 7) + ((lane >> 3) & 1) * 8) * HSTRIDE + (lane >> 4) * 8;
}
__device__ __forceinline__ int b_lane_off(int lane){
    return ((lane & 7) + (lane >> 4) * 8) * HSTRIDE + ((lane >> 3) & 1) * 8;
}

// ---------------------------------------------------------------- weight convert
__global__ void k_cvtw(const float* __restrict__ projw, const float* __restrict__ gatew,
                       const float* __restrict__ outw,  const float* __restrict__ gatingw)
{
    int idx = blockIdx.x*256 + threadIdx.x;
    int row = idx >> 4, q8 = idx & 15;
    const float* src;
    if (row < 512) {
        int c = row >> 2, q = row & 3;
        src = (q < 2) ? projw + (size_t)(2*c+q)*CH : gatew + (size_t)(2*c+q-2)*CH;
    } else if (row < 640) {
        src = outw + (size_t)(row-512)*CH;
    } else {
        src = gatingw + (size_t)(row-640)*CH;
    }
    float4 lo = *(const float4*)(src + q8*8);
    float4 hi = *(const float4*)(src + q8*8 + 4);
    *(uint4*)(g_wh + (size_t)row*CH + q8*8) = h8pack(lo, hi);
}

// ---------------------------------------------------------------- LN1 -> fp16 x
__global__ void k_ln1(const float* __restrict__ pair,
                      const float* __restrict__ w,
                      const float* __restrict__ b)
{
    int warp = threadIdx.x >> 5, lane = threadIdx.x & 31;
    size_t r = (size_t)blockIdx.x * 8 + warp;
    const float4* src = (const float4*)(pair + r * CH);
    float4 v = src[lane];
    float s = v.x + v.y + v.z + v.w;
    #pragma unroll
    for (int o = 16; o; o >>= 1) s += __shfl_xor_sync(0xffffffffu, s, o);
    float mu = s * (1.f/128.f);
    float dx = v.x-mu, dy = v.y-mu, dz = v.z-mu, dw = v.w-mu;
    float q = dx*dx + dy*dy + dz*dz + dw*dw;
    #pragma unroll
    for (int o = 16; o; o >>= 1) q += __shfl_xor_sync(0xffffffffu, q, o);
    float rstd = rsqrtf(q * (1.f/128.f) + 1e-5f);
    float4 wv = ((const float4*)w)[lane];
    float4 bv = ((const float4*)b)[lane];
    float4 o4;
    o4.x = dx*rstd*wv.x + bv.x;
    o4.y = dy*rstd*wv.y + bv.y;
    o4.z = dz*rstd*wv.z + bv.z;
    o4.w = dw*rstd*wv.w + bv.w;
    *(uint2*)(g_xh + r * CH + lane*4) = h4pack(o4);
}

// ---------------------------------------------------------------- proj+gate (streaming, resident W)
// grid (4, 576): cg = channel-group, each CTA streams 8 row-blocks of 128 rows.
// smem (halves): [0,2H)=W k0/k1 resident | [2H,5H)=X ring (3 slots) | [5H,+8704)=fp16 staging
#define PG_ITER 8
#define PG_NCH (PG_ITER*2)          // 16 chunks
#define PG_W   0
#define PG_X   (2*HBUF)
#define PG_STG (5*HBUF)
#define PG_SMEM ((5*HBUF + 2*32*136)*2)   // 109568 B

__global__ void __launch_bounds__(256, 2) k_projgate_mma(const float* __restrict__ mask)
{
    extern __shared__ __half hsm[];
    int tid = threadIdx.x, lane = tid & 31, warp = tid >> 5;
    int cg = blockIdx.x;
    int rb0 = blockIdx.y * PG_ITER;
    __half* ga = (__half*)g_ab;
    __half* gb = ga + (size_t)CH*RTOT;

    int wm = (warp >> 2) * 64;
    int wn = (warp & 3) * 32;

    float acc[4][4][4];
    #pragma unroll
    for (int mt = 0; mt < 4; mt++)
        #pragma unroll
        for (int nt = 0; nt < 4; nt++)
            #pragma unroll
            for (int e = 0; e < 4; e++) acc[mt][nt][e] = 0.f;

    const __half* W = g_wh + (size_t)(cg*128) * CH;

    // prologue group 0: W (both K-halves) + chunk 0
    #pragma unroll
    for (int l = 0; l < 8; l++) {
        int idx = tid + l*256;          // 0..2047
        int r = idx >> 4, q16 = idx & 15;
        int kh = q16 >> 3, q8 = q16 & 7;
        cpa16(hsm + PG_W + kh*HBUF + r*HSTRIDE + q8*8, W + (size_t)r*CH + q16*8);
    }
    {
        const __half* A0 = g_xh + (size_t)rb0 * 128 * CH;
        int r = tid >> 3, q = tid & 7;
        #pragma unroll
        for (int l = 0; l < 4; l++) {
            int rr = r + l*32;
            cpa16(hsm + PG_X + rr*HSTRIDE + q*8, A0 + (size_t)rr*CH + q*8);
        }
    }
    CPA_COMMIT();
    // prologue group 1: chunk 1 (same row-block, k 64..127)
    {
        const __half* A0 = g_xh + (size_t)rb0 * 128 * CH;
        int r = tid >> 3, q = tid & 7;
        #pragma unroll
        for (int l = 0; l < 4; l++) {
            int rr = r + l*32;
            cpa16(hsm + PG_X + HBUF + rr*HSTRIDE + q*8, A0 + (size_t)rr*CH + 64 + q*8);
        }
    }
    CPA_COMMIT();

    int ao = wm*HSTRIDE + a_lane_off(lane);
    int bo = wn*HSTRIDE + b_lane_off(lane);
    int crow = lane >> 2, ccol = (lane & 3) * 2;

    int buf = 0;
    for (int t = 0; t < PG_NCH; t++) {
        CPA_WAIT1();
        __syncthreads();

        if (t + 2 < PG_NCH) {
            int nt2 = t + 2;
            int rb = nt2 >> 1, kc = nt2 & 1;
            int nb = buf + 2; if (nb >= 3) nb -= 3;
            const __half* As = g_xh + ((size_t)(rb0 + rb) * 128) * CH + kc*64;
            int r = tid >> 3, q = tid & 7;
            #pragma unroll
            for (int l = 0; l < 4; l++) {
                int rr = r + l*32;
                cpa16(hsm + PG_X + nb*HBUF + rr*HSTRIDE + q*8, As + (size_t)rr*CH + q*8);
            }
            CPA_COMMIT();
        }

        const __half* cX = hsm + PG_X + buf*HBUF;
        const __half* cW = hsm + PG_W + (t & 1)*HBUF;
        #pragma unroll
        for (int ks = 0; ks < 4; ks++) {
            int kb = ks * 16;
            uint32_t af[4][4], bf[2][4];
            #pragma unroll
            for (int mt = 0; mt < 4; mt++) ldsm4(af[mt], cX + ao + mt*16*HSTRIDE + kb);
            #pragma unroll
            for (int np = 0; np < 2; np++) ldsm4(bf[np], cW + bo + np*16*HSTRIDE + kb);
            #pragma unroll
            for (int mt = 0; mt < 4; mt++)
                #pragma unroll
                for (int nt = 0; nt < 4; nt++)
                    mma16(acc[mt][nt], af[mt], &bf[nt>>1][(nt&1)*2]);
        }

        if (t & 1) {
            // epilogue for row-block rb = t>>1
            int rb = t >> 1;
            size_t i0 = (size_t)(rb0 + rb) * 128;
            int mbase = (int)(i0 % NTOK);
            __half* a_s = hsm + PG_STG;      // [32][136] fp16
            __half* b_s = a_s + 32*136;
            #pragma unroll
            for (int mt = 0; mt < 4; mt++) {
                #pragma unroll
                for (int nt = 0; nt < 4; nt++) {
                    float g0r1 = __shfl_xor_sync(0xffffffffu, acc[mt][nt][0], 1);
                    float g1r1 = __shfl_xor_sync(0xffffffffu, acc[mt][nt][1], 1);
                    float g0r2 = __shfl_xor_sync(0xffffffffu, acc[mt][nt][2], 1);
                    float g1r2 = __shfl_xor_sync(0xffffffffu, acc[mt][nt][3], 1);
                    if ((lane & 1) == 0) {
                        int j  = wn + nt*8 + ccol;
                        int cl = j >> 2;
                        int r1 = wm + mt*16 + crow, r2 = r1 + 8;
                        float mk1 = mask[mbase + r1], mk2 = mask[mbase + r2];
                        a_s[cl*136 + r1] = __float2half_rn(acc[mt][nt][0] * mk1 * sigm(g0r1));
                        b_s[cl*136 + r1] = __float2half_rn(acc[mt][nt][1] * mk1 * sigm(g1r1));
                        a_s[cl*136 + r2] = __float2half_rn(acc[mt][nt][2] * mk2 * sigm(g0r2));
                        b_s[cl*136 + r2] = __float2half_rn(acc[mt][nt][3] * mk2 * sigm(g1r2));
                    }
                }
            }
            __syncthreads();
            int cb = cg * 32;
            #pragma unroll
            for (int it = 0; it < 2; it++) {
                int idx = tid + it*256;          // ch(0..31) x f8(0..15)
                int ch = idx >> 4, f8 = idx & 15;
                *(uint4*)(ga + (size_t)(cb+ch)*RTOT + i0 + f8*8) = *(uint4*)(a_s + ch*136 + f8*8);
                *(uint4*)(gb + (size_t)(cb+ch)*RTOT + i0 + f8*8) = *(uint4*)(b_s + ch*136 + f8*8);
            }
            #pragma unroll
            for (int mt = 0; mt < 4; mt++)
                #pragma unroll
                for (int nt = 0; nt < 4; nt++)
                    #pragma unroll
                    for (int e = 0; e < 4; e++) acc[mt][nt][e] = 0.f;
        }
        buf++; if (buf >= 3) buf = 0;
    }
}

// ---------------------------------------------------------------- fp16 mma einsum (3-stage, 128x128 tile) -> fp16 out
#define KC 64
#define NCHUNK (NTOK/KC)           // 12
#define NSTAGE 3
#define DSMEM (NSTAGE*2*HBUF*2)    // 110592 B

__global__ void __launch_bounds__(256, 2) k_einsum_mma()
{
    extern __shared__ __half hsm[];
    int c  = blockIdx.z;
    int i0 = blockIdx.y * 128;
    int j0 = blockIdx.x * 128;
    const __half* ga = (const __half*)g_ab;
    const __half* gb = ga + (size_t)CH*RTOT;
    const __half* A = ga + (size_t)c*RTOT + (size_t)i0*NTOK;
    const __half* B = gb + (size_t)c*RTOT + (size_t)j0*NTOK;
    __half*       O = g_oh + (size_t)c*RTOT;

    int tid = threadIdx.x, lane = tid & 31, warp = tid >> 5;
    int wm = (warp >> 2) * 64;
    int wn = (warp & 3) * 32;

    float acc[4][4][4];
    #pragma unroll
    for (int mt = 0; mt < 4; mt++)
        #pragma unroll
        for (int nt = 0; nt < 4; nt++)
            #pragma unroll
            for (int e = 0; e < 4; e++) acc[mt][nt][e] = 0.f;

    int rr = tid >> 3, q = tid & 7;

    #pragma unroll
    for (int pc = 0; pc < 2; pc++) {
        __half* dA = hsm + pc*2*HBUF;
        __half* dB = dA + HBUF;
        const __half* As = A + pc*KC;
        const __half* Bs = B + pc*KC;
        #pragma unroll
        for (int l = 0; l < 4; l++) {
            int r = rr + l*32;
            cpa16(dA + r*HSTRIDE + q*8, As + (size_t)r*NTOK + q*8);
            cpa16(dB + r*HSTRIDE + q*8, Bs + (size_t)r*NTOK + q*8);
        }
        CPA_COMMIT();
    }

    int ao = wm*HSTRIDE + a_lane_off(lane);
    int bo = wn*HSTRIDE + b_lane_off(lane);

    int buf = 0;
    for (int kc = 0; kc < NCHUNK; kc++) {
        CPA_WAIT1();
        __syncthreads();

        if (kc + 2 < NCHUNK) {
            int nb = buf + 2; if (nb >= NSTAGE) nb -= NSTAGE;
            __half* dA = hsm + nb*2*HBUF;
            __half* dB = dA + HBUF;
            const __half* As = A + (kc+2)*KC;
            const __half* Bs = B + (kc+2)*KC;
            #pragma unroll
            for (int l = 0; l < 4; l++) {
                int r = rr + l*32;
                cpa16(dA + r*HSTRIDE + q*8, As + (size_t)r*NTOK + q*8);
                cpa16(dB + r*HSTRIDE + q*8, Bs + (size_t)r*NTOK + q*8);
            }
            CPA_COMMIT();
        }

        const __half* cA = hsm + buf*2*HBUF;
        const __half* cB = cA + HBUF;
        #pragma unroll
        for (int ks = 0; ks < 4; ks++) {
            int kb = ks * 16;
            uint32_t af[4][4], bf[2][4];
            #pragma unroll
            for (int mt = 0; mt < 4; mt++) ldsm4(af[mt], cA + ao + mt*16*HSTRIDE + kb);
            #pragma unroll
            for (int np = 0; np < 2; np++) ldsm4(bf[np], cB + bo + np*16*HSTRIDE + kb);
            #pragma unroll
            for (int mt = 0; mt < 4; mt++)
                #pragma unroll
                for (int nt = 0; nt < 4; nt++)
                    mma16(acc[mt][nt], af[mt], &bf[nt>>1][(nt&1)*2]);
        }
        buf++; if (buf >= NSTAGE) buf = 0;
    }

    int crow = lane >> 2, ccol = (lane & 3) * 2;
    #pragma unroll
    for (int mt = 0; mt < 4; mt++) {
        #pragma unroll
        for (int nt = 0; nt < 4; nt++) {
            __half* d0 = O + (size_t)(i0 + wm + mt*16 + crow)*NTOK + j0 + wn + nt*8 + ccol;
            *(uint32_t*)d0 = h2pack(acc[mt][nt][0], acc[mt][nt][1]);
            *(uint32_t*)(d0 + 8*NTOK) = h2pack(acc[mt][nt][2], acc[mt][nt][3]);
        }
    }
}

// ---------------------------------------------------------------- LN2 + transpose (fp16 in, fp16 out)
__global__ void k_ln2t(const float* __restrict__ w, const float* __restrict__ b)
{
    __shared__ float t[128*36];
    __shared__ float red[8][33];
    __shared__ float mu_s[32], rstd_s[32];
    __shared__ float w_s[128], b_s[128];
    int tid = threadIdx.x;
    size_t r0 = (size_t)blockIdx.x * 32;

    if (tid < 128) { w_s[tid] = w[tid]; b_s[tid] = b[tid]; }

    #pragma unroll
    for (int it = 0; it < 2; it++) {
        int idx = tid + it*256;            // c(0..127) x rq(0..3), 8 halves each
        int c = idx >> 2, rq = idx & 3;
        uint4 v = *(const uint4*)(g_oh + (size_t)c*RTOT + r0 + rq*8);
        float* dst = t + c*36 + rq*8;
        float2 f0 = __half22float2(*(__half2*)&v.x);
        float2 f1 = __half22float2(*(__half2*)&v.y);
        float2 f2 = __half22float2(*(__half2*)&v.z);
        float2 f3 = __half22float2(*(__half2*)&v.w);
        dst[0] = f0.x; dst[1] = f0.y;
        dst[2] = f1.x; dst[3] = f1.y;
        dst[4] = f2.x; dst[5] = f2.y;
        dst[6] = f3.x; dst[7] = f3.y;
    }
    __syncthreads();

    int rr = tid & 31, part = tid >> 5;
    float s = 0.f;
    #pragma unroll
    for (int k = 0; k < 16; k++) s += t[(part*16 + k)*36 + rr];
    red[part][rr] = s;
    __syncthreads();
    if (tid < 32) {
        float tot = 0.f;
        #pragma unroll
        for (int p = 0; p < 8; p++) tot += red[p][tid];
        mu_s[tid] = tot * (1.f/128.f);
    }
    __syncthreads();
    float mu = mu_s[rr], qv = 0.f;
    #pragma unroll
    for (int k = 0; k < 16; k++) {
        float d = t[(part*16 + k)*36 + rr] - mu; qv += d*d;
    }
    __syncthreads();
    red[part][rr] = qv;
    __syncthreads();
    if (tid < 32) {
        float tot = 0.f;
        #pragma unroll
        for (int p = 0; p < 8; p++) tot += red[p][tid];
        rstd_s[tid] = rsqrtf(tot * (1.f/128.f) + 1e-5f);
    }
    __syncthreads();

    float rstd = rstd_s[rr];
    mu = mu_s[rr];
    __half* u = (__half*)g_ab;   // ga/gb dead: reuse as fp16 u buffer [r][c]
    float f[16];
    #pragma unroll
    for (int k = 0; k < 16; k++) {
        int c = part*16 + k;
        f[k] = (t[c*36 + rr] - mu) * rstd * w_s[c] + b_s[c];
    }
    __half* dst = u + (r0 + rr)*CH + part*16;
    *(uint4*)(dst)     = h8pack(make_float4(f[0],f[1],f[2],f[3]),   make_float4(f[4],f[5],f[6],f[7]));
    *(uint4*)(dst + 8) = h8pack(make_float4(f[8],f[9],f[10],f[11]), make_float4(f[12],f[13],f[14],f[15]));
}

// ---------------------------------------------------------------- final (streaming, resident Wo/Wg)
// grid 576: each CTA streams 8 row-blocks. smem (halves):
// [0,4H)=Wo k0/k1, Wg k0/k1 resident | [4H,10H)=U/X ring (3 slots x 2 tiles)
#define FN_ITER 8
#define FN_NCH (FN_ITER*2)          // 16 chunks
#define FN_W  0
#define FN_UX (4*HBUF)
#define FN_SMEM (10*HBUF*2)         // 184320 B

__global__ void __launch_bounds__(256, 1) k_final_mma(float* __restrict__ out)
{
    extern __shared__ __half hsm[];
    int tid = threadIdx.x, lane = tid & 31, warp = tid >> 5;
    int rb0 = blockIdx.x * FN_ITER;
    const __half* U0 = (const __half*)g_ab;
    const __half* X0 = g_xh;
    const __half* Wo = g_wh + (size_t)512*CH;
    const __half* Wg = g_wh + (size_t)640*CH;

    int wm = (warp >> 2) * 64;
    int wn = (warp & 3) * 32;

    float accU[4][4][4], accX[4][4][4];
    #pragma unroll
    for (int mt = 0; mt < 4; mt++)
        #pragma unroll
        for (int nt = 0; nt < 4; nt++)
            #pragma unroll
            for (int e = 0; e < 4; e++) { accU[mt][nt][e] = 0.f; accX[mt][nt][e] = 0.f; }

    // prologue group 0: all weights + chunk 0 (U,X of row-block 0, k 0..63)
    #pragma unroll
    for (int l = 0; l < 16; l++) {
        int idx = tid + l*256;          // 0..4095
        int t4 = idx >> 10;             // 0..3 : Wo_k0, Wo_k1, Wg_k0, Wg_k1
        int j = idx & 1023;
        int r = j >> 3, q8 = j & 7;
        const __half* src = ((t4 < 2) ? Wo : Wg) + (size_t)r*CH + (t4 & 1)*64 + q8*8;
        cpa16(hsm + FN_W + t4*HBUF + r*HSTRIDE + q8*8, src);
    }
    {
        const __half* Ub = U0 + (size_t)rb0 * 128 * CH;
        const __half* Xb = X0 + (size_t)rb0 * 128 * CH;
        int r = tid >> 3, q = tid & 7;
        #pragma unroll
        for (int l = 0; l < 4; l++) {
            int rr = r + l*32;
            cpa16(hsm + FN_UX + rr*HSTRIDE + q*8, Ub + (size_t)rr*CH + q*8);
            cpa16(hsm + FN_UX + HBUF + rr*HSTRIDE + q*8, Xb + (size_t)rr*CH + q*8);
        }
    }
    CPA_COMMIT();
    // prologue group 1: chunk 1 (row-block 0, k 64..127)
    {
        const __half* Ub = U0 + (size_t)rb0 * 128 * CH;
        const __half* Xb = X0 + (size_t)rb0 * 128 * CH;
        int r = tid >> 3, q = tid & 7;
        #pragma unroll
        for (int l = 0; l < 4; l++) {
            int rr = r + l*32;
            cpa16(hsm + FN_UX + 2*HBUF + rr*HSTRIDE + q*8, Ub + (size_t)rr*CH + 64 + q*8);
            cpa16(hsm + FN_UX + 3*HBUF + rr*HSTRIDE + q*8, Xb + (size_t)rr*CH + 64 + q*8);
        }
    }
    CPA_COMMIT();

    int ao = wm*HSTRIDE + a_lane_off(lane);
    int bo = wn*HSTRIDE + b_lane_off(lane);
    int crow = lane >> 2, ccol = (lane & 3) * 2;

    int buf = 0;
    for (int t = 0; t < FN_NCH; t++) {
        CPA_WAIT1();
        __syncthreads();

        if (t + 2 < FN_NCH) {
            int nt2 = t + 2;
            int rb = nt2 >> 1, kc = nt2 & 1;
            int nb = buf + 2; if (nb >= 3) nb -= 3;
            const __half* Ub = U0 + ((size_t)(rb0 + rb) * 128) * CH + kc*64;
            const __half* Xb = X0 + ((size_t)(rb0 + rb) * 128) * CH + kc*64;
            int r = tid >> 3, q = tid & 7;
            #pragma unroll
            for (int l = 0; l < 4; l++) {
                int rr = r + l*32;
                cpa16(hsm + FN_UX + nb*2*HBUF + rr*HSTRIDE + q*8, Ub + (size_t)rr*CH + q*8);
                cpa16(hsm + FN_UX + nb*2*HBUF + HBUF + rr*HSTRIDE + q*8, Xb + (size_t)rr*CH + q*8);
            }
            CPA_COMMIT();
        }

        const __half* cU = hsm + FN_UX + buf*2*HBUF;
        const __half* cX = cU + HBUF;
        const __half* cWo = hsm + FN_W + (t & 1)*HBUF;
        const __half* cWg = hsm + FN_W + 2*HBUF + (t & 1)*HBUF;
        #pragma unroll
        for (int ks = 0; ks < 4; ks++) {
            int kb = ks * 16;
            uint32_t au[4][4], ax[4][4], bo2[2][4], bg2[2][4];
            #pragma unroll
            for (int mt = 0; mt < 4; mt++) {
                ldsm4(au[mt], cU + ao + mt*16*HSTRIDE + kb);
                ldsm4(ax[mt], cX + ao + mt*16*HSTRIDE + kb);
            }
            #pragma unroll
            for (int np = 0; np < 2; np++) {
                ldsm4(bo2[np], cWo + bo + np*16*HSTRIDE + kb);
                ldsm4(bg2[np], cWg + bo + np*16*HSTRIDE + kb);
            }
            #pragma unroll
            for (int mt = 0; mt < 4; mt++)
                #pragma unroll
                for (int nt = 0; nt < 4; nt++) {
                    mma16(accU[mt][nt], au[mt], &bo2[nt>>1][(nt&1)*2]);
                    mma16(accX[mt][nt], ax[mt], &bg2[nt>>1][(nt&1)*2]);
                }
        }

        if (t & 1) {
            size_t i0 = (size_t)(rb0 + (t >> 1)) * 128;
            #pragma unroll
            for (int mt = 0; mt < 4; mt++) {
                #pragma unroll
                for (int nt = 0; nt < 4; nt++) {
                    size_t r1 = i0 + wm + mt*16 + crow;
                    int col = wn + nt*8 + ccol;
                    float2 v0, v1;
                    v0.x = accU[mt][nt][0] * sigm(accX[mt][nt][0]);
                    v0.y = accU[mt][nt][1] * sigm(accX[mt][nt][1]);
                    v1.x = accU[mt][nt][2] * sigm(accX[mt][nt][2]);
                    v1.y = accU[mt][nt][3] * sigm(accX[mt][nt][3]);
                    *(float2*)(out + r1*CH + col) = v0;
                    *(float2*)(out + (r1+8)*CH + col) = v1;
                }
            }
            #pragma unroll
            for (int mt = 0; mt < 4; mt++)
                #pragma unroll
                for (int nt = 0; nt < 4; nt++)
                    #pragma unroll
                    for (int e = 0; e < 4; e++) { accU[mt][nt][e] = 0.f; accX[mt][nt][e] = 0.f; }
        }
        buf++; if (buf >= 3) buf = 0;
    }
}

// ---------------------------------------------------------------- launch
extern "C" void kernel_launch(void* const* d_in, const int* in_sizes, int n_in,
                              void* d_out, int out_size)
{
    const float* pair     = (const float*)d_in[0];
    const float* mask     = (const float*)d_in[1];
    const float* ln1_w    = (const float*)d_in[2];
    const float* ln1_b    = (const float*)d_in[3];
    const float* proj_w   = (const float*)d_in[4];
    const float* gate_w   = (const float*)d_in[5];
    const float* ln2_w    = (const float*)d_in[6];
    const float* ln2_b    = (const float*)d_in[7];
    const float* out_w    = (const float*)d_in[8];
    const float* gating_w = (const float*)d_in[9];
    float* out = (float*)d_out;

    cudaFuncSetAttribute(k_projgate_mma, cudaFuncAttributeMaxDynamicSharedMemorySize, PG_SMEM);
    cudaFuncSetAttribute(k_einsum_mma,   cudaFuncAttributeMaxDynamicSharedMemorySize, DSMEM);
    cudaFuncSetAttribute(k_final_mma,    cudaFuncAttributeMaxDynamicSharedMemorySize, FN_SMEM);

    k_cvtw<<<48, 256>>>(proj_w, gate_w, out_w, gating_w);
    k_ln1<<<RTOT/8, 256>>>(pair, ln1_w, ln1_b);
    k_projgate_mma<<<dim3(4, RTOT/128/PG_ITER), 256, PG_SMEM>>>(mask);
    k_einsum_mma<<<dim3(NTOK/128, NTOK/128, CH), 256, DSMEM>>>();
    k_ln2t<<<RTOT/32, 256>>>(ln2_w, ln2_b);
    k_final_mma<<<RTOT/128/FN_ITER, 256, FN_SMEM>>>(out);
}

// round 17
// speedup vs baseline: 1.0881x; 1.0155x over previous
#include <cuda_runtime.h>
#include <cuda_fp16.h>
#include <math.h>
#include <stdint.h>

// TriangleMultiplication: N=768, C=128 — fp16 tensor-core pipeline + cp.async + ldmatrix
//   k_cvtw         : weights -> fp16
//   k_ln1          : x = LN(pair) (4 rows/warp, MLP4)        -> g_xh [r][c] fp16
//   k_projgate_mma : streaming row-blocks, resident W        -> ga,gb [c][r] fp16
//   k_einsum_mma   : out_c = A_c @ B_c^T per channel (fp16, 3-stage) -> g_oh [c][i][j] fp16
//   k_ln2t         : u = LN_c(out) transposed                -> u (= g_ab reuse) fp16 [r][c]
//   k_final_mma    : streaming 32 row-blocks (single wave), resident Wo/Wg -> d_out f32

#define NTOK 768
#define CH   128
#define RTOT (NTOK*NTOK)   // 589824

__device__ __half g_xh[(size_t)RTOT*CH];
__device__ __half g_oh[(size_t)CH*RTOT];
__device__ __align__(256) unsigned char g_ab[(size_t)CH*RTOT*4];
__device__ __half g_wh[768*CH];   // [0,512)=proj/gate interleaved, [512,640)=out_w, [640,768)=gating_w

__device__ __forceinline__ float sigm(float v){ return 1.f/(1.f+expf(-v)); }

__device__ __forceinline__ void mma16(float* d, const uint32_t* a, const uint32_t* b){
    asm volatile(
        "mma.sync.aligned.m16n8k16.row.col.f32.f16.f16.f32 "
        "{%0,%1,%2,%3}, {%4,%5,%6,%7}, {%8,%9}, {%0,%1,%2,%3};"
        : "+f"(d[0]), "+f"(d[1]), "+f"(d[2]), "+f"(d[3])
        : "r"(a[0]), "r"(a[1]), "r"(a[2]), "r"(a[3]), "r"(b[0]), "r"(b[1]));
}

__device__ __forceinline__ void ldsm4(uint32_t* r, const __half* p){
    uint32_t a;
    asm("{ .reg .u64 t; cvta.to.shared.u64 t, %1; cvt.u32.u64 %0, t; }" : "=r"(a) : "l"(p));
    asm volatile("ldmatrix.sync.aligned.m8n8.x4.shared.b16 {%0,%1,%2,%3}, [%4];"
        : "=r"(r[0]), "=r"(r[1]), "=r"(r[2]), "=r"(r[3]) : "r"(a));
}

__device__ __forceinline__ uint32_t h2pack(float a, float b){
    __half2 h = __floats2half2_rn(a, b);
    return *(uint32_t*)&h;
}
__device__ __forceinline__ uint4 h8pack(float4 lo, float4 hi){
    uint4 r;
    r.x = h2pack(lo.x, lo.y);
    r.y = h2pack(lo.z, lo.w);
    r.z = h2pack(hi.x, hi.y);
    r.w = h2pack(hi.z, hi.w);
    return r;
}
__device__ __forceinline__ uint2 h4pack(float4 v){
    uint2 r;
    r.x = h2pack(v.x, v.y);
    r.y = h2pack(v.z, v.w);
    return r;
}

__device__ __forceinline__ void cpa16(__half* dst, const __half* src){
    uint32_t s;
    asm("{ .reg .u64 t; cvta.to.shared.u64 t, %1; cvt.u32.u64 %0, t; }" : "=r"(s) : "l"(dst));
    asm volatile("cp.async.cg.shared.global [%0], [%1], 16;" :: "r"(s), "l"(src));
}
#define CPA_COMMIT() asm volatile("cp.async.commit_group;" ::: "memory")
#define CPA_WAIT0()  asm volatile("cp.async.wait_group 0;" ::: "memory")
#define CPA_WAIT1()  asm volatile("cp.async.wait_group 1;" ::: "memory")

#define HSTRIDE 72
#define HBUF (128*HSTRIDE)    // halves per 128x64 tile

__device__ __forceinline__ int a_lane_off(int lane){
    return ((lane & 7) + ((lane >> 3) & 1) * 8) * HSTRIDE + (lane >> 4) * 8;
}
__device__ __forceinline__ int b_lane_off(int lane){
    return ((lane & 7) + (lane >> 4) * 8) * HSTRIDE + ((lane >> 3) & 1) * 8;
}

// ---------------------------------------------------------------- weight convert
__global__ void k_cvtw(const float* __restrict__ projw, const float* __restrict__ gatew,
                       const float* __restrict__ outw,  const float* __restrict__ gatingw)
{
    int idx = blockIdx.x*256 + threadIdx.x;
    int row = idx >> 4, q8 = idx & 15;
    const float* src;
    if (row < 512) {
        int c = row >> 2, q = row & 3;
        src = (q < 2) ? projw + (size_t)(2*c+q)*CH : gatew + (size_t)(2*c+q-2)*CH;
    } else if (row < 640) {
        src = outw + (size_t)(row-512)*CH;
    } else {
        src = gatingw + (size_t)(row-640)*CH;
    }
    float4 lo = *(const float4*)(src + q8*8);
    float4 hi = *(const float4*)(src + q8*8 + 4);
    *(uint4*)(g_wh + (size_t)row*CH + q8*8) = h8pack(lo, hi);
}

// ---------------------------------------------------------------- LN1 -> fp16 x (4 rows/warp, batched loads)
__global__ void k_ln1(const float* __restrict__ pair,
                      const float* __restrict__ w,
                      const float* __restrict__ b)
{
    int warp = threadIdx.x >> 5, lane = threadIdx.x & 31;
    size_t r0 = (size_t)blockIdx.x * 32 + warp * 4;

    float4 v[4];
    #pragma unroll
    for (int i = 0; i < 4; i++)
        v[i] = ((const float4*)(pair + (r0 + i) * CH))[lane];

    float4 wv = ((const float4*)w)[lane];
    float4 bv = ((const float4*)b)[lane];

    float s[4];
    #pragma unroll
    for (int i = 0; i < 4; i++) s[i] = v[i].x + v[i].y + v[i].z + v[i].w;
    #pragma unroll
    for (int o = 16; o; o >>= 1)
        #pragma unroll
        for (int i = 0; i < 4; i++) s[i] += __shfl_xor_sync(0xffffffffu, s[i], o);

    float mu[4], q[4];
    #pragma unroll
    for (int i = 0; i < 4; i++) {
        mu[i] = s[i] * (1.f/128.f);
        float dx = v[i].x - mu[i], dy = v[i].y - mu[i], dz = v[i].z - mu[i], dw = v[i].w - mu[i];
        q[i] = dx*dx + dy*dy + dz*dz + dw*dw;
    }
    #pragma unroll
    for (int o = 16; o; o >>= 1)
        #pragma unroll
        for (int i = 0; i < 4; i++) q[i] += __shfl_xor_sync(0xffffffffu, q[i], o);

    #pragma unroll
    for (int i = 0; i < 4; i++) {
        float rstd = rsqrtf(q[i] * (1.f/128.f) + 1e-5f);
        float4 o4;
        o4.x = (v[i].x - mu[i])*rstd*wv.x + bv.x;
        o4.y = (v[i].y - mu[i])*rstd*wv.y + bv.y;
        o4.z = (v[i].z - mu[i])*rstd*wv.z + bv.z;
        o4.w = (v[i].w - mu[i])*rstd*wv.w + bv.w;
        *(uint2*)(g_xh + (r0 + i) * CH + lane*4) = h4pack(o4);
    }
}

// ---------------------------------------------------------------- proj+gate (streaming, resident W)
#define PG_ITER 8
#define PG_NCH (PG_ITER*2)          // 16 chunks
#define PG_W   0
#define PG_X   (2*HBUF)
#define PG_STG (5*HBUF)
#define PG_SMEM ((5*HBUF + 2*32*136)*2)   // 109568 B

__global__ void __launch_bounds__(256, 2) k_projgate_mma(const float* __restrict__ mask)
{
    extern __shared__ __half hsm[];
    int tid = threadIdx.x, lane = tid & 31, warp = tid >> 5;
    int cg = blockIdx.x;
    int rb0 = blockIdx.y * PG_ITER;
    __half* ga = (__half*)g_ab;
    __half* gb = ga + (size_t)CH*RTOT;

    int wm = (warp >> 2) * 64;
    int wn = (warp & 3) * 32;

    float acc[4][4][4];
    #pragma unroll
    for (int mt = 0; mt < 4; mt++)
        #pragma unroll
        for (int nt = 0; nt < 4; nt++)
            #pragma unroll
            for (int e = 0; e < 4; e++) acc[mt][nt][e] = 0.f;

    const __half* W = g_wh + (size_t)(cg*128) * CH;

    #pragma unroll
    for (int l = 0; l < 8; l++) {
        int idx = tid + l*256;
        int r = idx >> 4, q16 = idx & 15;
        int kh = q16 >> 3, q8 = q16 & 7;
        cpa16(hsm + PG_W + kh*HBUF + r*HSTRIDE + q8*8, W + (size_t)r*CH + q16*8);
    }
    {
        const __half* A0 = g_xh + (size_t)rb0 * 128 * CH;
        int r = tid >> 3, q = tid & 7;
        #pragma unroll
        for (int l = 0; l < 4; l++) {
            int rr = r + l*32;
            cpa16(hsm + PG_X + rr*HSTRIDE + q*8, A0 + (size_t)rr*CH + q*8);
        }
    }
    CPA_COMMIT();
    {
        const __half* A0 = g_xh + (size_t)rb0 * 128 * CH;
        int r = tid >> 3, q = tid & 7;
        #pragma unroll
        for (int l = 0; l < 4; l++) {
            int rr = r + l*32;
            cpa16(hsm + PG_X + HBUF + rr*HSTRIDE + q*8, A0 + (size_t)rr*CH + 64 + q*8);
        }
    }
    CPA_COMMIT();

    int ao = wm*HSTRIDE + a_lane_off(lane);
    int bo = wn*HSTRIDE + b_lane_off(lane);
    int crow = lane >> 2, ccol = (lane & 3) * 2;

    int buf = 0;
    for (int t = 0; t < PG_NCH; t++) {
        CPA_WAIT1();
        __syncthreads();

        if (t + 2 < PG_NCH) {
            int nt2 = t + 2;
            int rb = nt2 >> 1, kc = nt2 & 1;
            int nb = buf + 2; if (nb >= 3) nb -= 3;
            const __half* As = g_xh + ((size_t)(rb0 + rb) * 128) * CH + kc*64;
            int r = tid >> 3, q = tid & 7;
            #pragma unroll
            for (int l = 0; l < 4; l++) {
                int rr = r + l*32;
                cpa16(hsm + PG_X + nb*HBUF + rr*HSTRIDE + q*8, As + (size_t)rr*CH + q*8);
            }
            CPA_COMMIT();
        }

        const __half* cX = hsm + PG_X + buf*HBUF;
        const __half* cW = hsm + PG_W + (t & 1)*HBUF;
        #pragma unroll
        for (int ks = 0; ks < 4; ks++) {
            int kb = ks * 16;
            uint32_t af[4][4], bf[2][4];
            #pragma unroll
            for (int mt = 0; mt < 4; mt++) ldsm4(af[mt], cX + ao + mt*16*HSTRIDE + kb);
            #pragma unroll
            for (int np = 0; np < 2; np++) ldsm4(bf[np], cW + bo + np*16*HSTRIDE + kb);
            #pragma unroll
            for (int mt = 0; mt < 4; mt++)
                #pragma unroll
                for (int nt = 0; nt < 4; nt++)
                    mma16(acc[mt][nt], af[mt], &bf[nt>>1][(nt&1)*2]);
        }

        if (t & 1) {
            int rb = t >> 1;
            size_t i0 = (size_t)(rb0 + rb) * 128;
            int mbase = (int)(i0 % NTOK);
            __half* a_s = hsm + PG_STG;      // [32][136] fp16
            __half* b_s = a_s + 32*136;
            #pragma unroll
            for (int mt = 0; mt < 4; mt++) {
                #pragma unroll
                for (int nt = 0; nt < 4; nt++) {
                    float g0r1 = __shfl_xor_sync(0xffffffffu, acc[mt][nt][0], 1);
                    float g1r1 = __shfl_xor_sync(0xffffffffu, acc[mt][nt][1], 1);
                    float g0r2 = __shfl_xor_sync(0xffffffffu, acc[mt][nt][2], 1);
                    float g1r2 = __shfl_xor_sync(0xffffffffu, acc[mt][nt][3], 1);
                    if ((lane & 1) == 0) {
                        int j  = wn + nt*8 + ccol;
                        int cl = j >> 2;
                        int r1 = wm + mt*16 + crow, r2 = r1 + 8;
                        float mk1 = mask[mbase + r1], mk2 = mask[mbase + r2];
                        a_s[cl*136 + r1] = __float2half_rn(acc[mt][nt][0] * mk1 * sigm(g0r1));
                        b_s[cl*136 + r1] = __float2half_rn(acc[mt][nt][1] * mk1 * sigm(g1r1));
                        a_s[cl*136 + r2] = __float2half_rn(acc[mt][nt][2] * mk2 * sigm(g0r2));
                        b_s[cl*136 + r2] = __float2half_rn(acc[mt][nt][3] * mk2 * sigm(g1r2));
                    }
                }
            }
            __syncthreads();
            int cb = cg * 32;
            #pragma unroll
            for (int it = 0; it < 2; it++) {
                int idx = tid + it*256;
                int ch = idx >> 4, f8 = idx & 15;
                *(uint4*)(ga + (size_t)(cb+ch)*RTOT + i0 + f8*8) = *(uint4*)(a_s + ch*136 + f8*8);
                *(uint4*)(gb + (size_t)(cb+ch)*RTOT + i0 + f8*8) = *(uint4*)(b_s + ch*136 + f8*8);
            }
            #pragma unroll
            for (int mt = 0; mt < 4; mt++)
                #pragma unroll
                for (int nt = 0; nt < 4; nt++)
                    #pragma unroll
                    for (int e = 0; e < 4; e++) acc[mt][nt][e] = 0.f;
        }
        buf++; if (buf >= 3) buf = 0;
    }
}

// ---------------------------------------------------------------- fp16 mma einsum (3-stage, 128x128 tile) -> fp16 out
#define KC 64
#define NCHUNK (NTOK/KC)           // 12
#define NSTAGE 3
#define DSMEM (NSTAGE*2*HBUF*2)    // 110592 B

__global__ void __launch_bounds__(256, 2) k_einsum_mma()
{
    extern __shared__ __half hsm[];
    int c  = blockIdx.z;
    int i0 = blockIdx.y * 128;
    int j0 = blockIdx.x * 128;
    const __half* ga = (const __half*)g_ab;
    const __half* gb = ga + (size_t)CH*RTOT;
    const __half* A = ga + (size_t)c*RTOT + (size_t)i0*NTOK;
    const __half* B = gb + (size_t)c*RTOT + (size_t)j0*NTOK;
    __half*       O = g_oh + (size_t)c*RTOT;

    int tid = threadIdx.x, lane = tid & 31, warp = tid >> 5;
    int wm = (warp >> 2) * 64;
    int wn = (warp & 3) * 32;

    float acc[4][4][4];
    #pragma unroll
    for (int mt = 0; mt < 4; mt++)
        #pragma unroll
        for (int nt = 0; nt < 4; nt++)
            #pragma unroll
            for (int e = 0; e < 4; e++) acc[mt][nt][e] = 0.f;

    int rr = tid >> 3, q = tid & 7;

    #pragma unroll
    for (int pc = 0; pc < 2; pc++) {
        __half* dA = hsm + pc*2*HBUF;
        __half* dB = dA + HBUF;
        const __half* As = A + pc*KC;
        const __half* Bs = B + pc*KC;
        #pragma unroll
        for (int l = 0; l < 4; l++) {
            int r = rr + l*32;
            cpa16(dA + r*HSTRIDE + q*8, As + (size_t)r*NTOK + q*8);
            cpa16(dB + r*HSTRIDE + q*8, Bs + (size_t)r*NTOK + q*8);
        }
        CPA_COMMIT();
    }

    int ao = wm*HSTRIDE + a_lane_off(lane);
    int bo = wn*HSTRIDE + b_lane_off(lane);

    int buf = 0;
    for (int kc = 0; kc < NCHUNK; kc++) {
        CPA_WAIT1();
        __syncthreads();

        if (kc + 2 < NCHUNK) {
            int nb = buf + 2; if (nb >= NSTAGE) nb -= NSTAGE;
            __half* dA = hsm + nb*2*HBUF;
            __half* dB = dA + HBUF;
            const __half* As = A + (kc+2)*KC;
            const __half* Bs = B + (kc+2)*KC;
            #pragma unroll
            for (int l = 0; l < 4; l++) {
                int r = rr + l*32;
                cpa16(dA + r*HSTRIDE + q*8, As + (size_t)r*NTOK + q*8);
                cpa16(dB + r*HSTRIDE + q*8, Bs + (size_t)r*NTOK + q*8);
            }
            CPA_COMMIT();
        }

        const __half* cA = hsm + buf*2*HBUF;
        const __half* cB = cA + HBUF;
        #pragma unroll
        for (int ks = 0; ks < 4; ks++) {
            int kb = ks * 16;
            uint32_t af[4][4], bf[2][4];
            #pragma unroll
            for (int mt = 0; mt < 4; mt++) ldsm4(af[mt], cA + ao + mt*16*HSTRIDE + kb);
            #pragma unroll
            for (int np = 0; np < 2; np++) ldsm4(bf[np], cB + bo + np*16*HSTRIDE + kb);
            #pragma unroll
            for (int mt = 0; mt < 4; mt++)
                #pragma unroll
                for (int nt = 0; nt < 4; nt++)
                    mma16(acc[mt][nt], af[mt], &bf[nt>>1][(nt&1)*2]);
        }
        buf++; if (buf >= NSTAGE) buf = 0;
    }

    int crow = lane >> 2, ccol = (lane & 3) * 2;
    #pragma unroll
    for (int mt = 0; mt < 4; mt++) {
        #pragma unroll
        for (int nt = 0; nt < 4; nt++) {
            __half* d0 = O + (size_t)(i0 + wm + mt*16 + crow)*NTOK + j0 + wn + nt*8 + ccol;
            *(uint32_t*)d0 = h2pack(acc[mt][nt][0], acc[mt][nt][1]);
            *(uint32_t*)(d0 + 8*NTOK) = h2pack(acc[mt][nt][2], acc[mt][nt][3]);
        }
    }
}

// ---------------------------------------------------------------- LN2 + transpose (fp16 in, fp16 out)
__global__ void k_ln2t(const float* __restrict__ w, const float* __restrict__ b)
{
    __shared__ float t[128*36];
    __shared__ float red[8][33];
    __shared__ float mu_s[32], rstd_s[32];
    __shared__ float w_s[128], b_s[128];
    int tid = threadIdx.x;
    size_t r0 = (size_t)blockIdx.x * 32;

    if (tid < 128) { w_s[tid] = w[tid]; b_s[tid] = b[tid]; }

    #pragma unroll
    for (int it = 0; it < 2; it++) {
        int idx = tid + it*256;
        int c = idx >> 2, rq = idx & 3;
        uint4 v = *(const uint4*)(g_oh + (size_t)c*RTOT + r0 + rq*8);
        float* dst = t + c*36 + rq*8;
        float2 f0 = __half22float2(*(__half2*)&v.x);
        float2 f1 = __half22float2(*(__half2*)&v.y);
        float2 f2 = __half22float2(*(__half2*)&v.z);
        float2 f3 = __half22float2(*(__half2*)&v.w);
        dst[0] = f0.x; dst[1] = f0.y;
        dst[2] = f1.x; dst[3] = f1.y;
        dst[4] = f2.x; dst[5] = f2.y;
        dst[6] = f3.x; dst[7] = f3.y;
    }
    __syncthreads();

    int rr = tid & 31, part = tid >> 5;
    float s = 0.f;
    #pragma unroll
    for (int k = 0; k < 16; k++) s += t[(part*16 + k)*36 + rr];
    red[part][rr] = s;
    __syncthreads();
    if (tid < 32) {
        float tot = 0.f;
        #pragma unroll
        for (int p = 0; p < 8; p++) tot += red[p][tid];
        mu_s[tid] = tot * (1.f/128.f);
    }
    __syncthreads();
    float mu = mu_s[rr], qv = 0.f;
    #pragma unroll
    for (int k = 0; k < 16; k++) {
        float d = t[(part*16 + k)*36 + rr] - mu; qv += d*d;
    }
    __syncthreads();
    red[part][rr] = qv;
    __syncthreads();
    if (tid < 32) {
        float tot = 0.f;
        #pragma unroll
        for (int p = 0; p < 8; p++) tot += red[p][tid];
        rstd_s[tid] = rsqrtf(tot * (1.f/128.f) + 1e-5f);
    }
    __syncthreads();

    float rstd = rstd_s[rr];
    mu = mu_s[rr];
    __half* u = (__half*)g_ab;   // ga/gb dead: reuse as fp16 u buffer [r][c]
    float f[16];
    #pragma unroll
    for (int k = 0; k < 16; k++) {
        int c = part*16 + k;
        f[k] = (t[c*36 + rr] - mu) * rstd * w_s[c] + b_s[c];
    }
    __half* dst = u + (r0 + rr)*CH + part*16;
    *(uint4*)(dst)     = h8pack(make_float4(f[0],f[1],f[2],f[3]),   make_float4(f[4],f[5],f[6],f[7]));
    *(uint4*)(dst + 8) = h8pack(make_float4(f[8],f[9],f[10],f[11]), make_float4(f[12],f[13],f[14],f[15]));
}

// ---------------------------------------------------------------- final (streaming 32 row-blocks, single wave)
#define FN_ITER 32
#define FN_NCH (FN_ITER*2)          // 64 chunks
#define FN_W  0
#define FN_UX (4*HBUF)
#define FN_SMEM (10*HBUF*2)         // 184320 B

__global__ void __launch_bounds__(256, 1) k_final_mma(float* __restrict__ out)
{
    extern __shared__ __half hsm[];
    int tid = threadIdx.x, lane = tid & 31, warp = tid >> 5;
    int rb0 = blockIdx.x * FN_ITER;
    const __half* U0 = (const __half*)g_ab;
    const __half* X0 = g_xh;
    const __half* Wo = g_wh + (size_t)512*CH;
    const __half* Wg = g_wh + (size_t)640*CH;

    int wm = (warp >> 2) * 64;
    int wn = (warp & 3) * 32;

    float accU[4][4][4], accX[4][4][4];
    #pragma unroll
    for (int mt = 0; mt < 4; mt++)
        #pragma unroll
        for (int nt = 0; nt < 4; nt++)
            #pragma unroll
            for (int e = 0; e < 4; e++) { accU[mt][nt][e] = 0.f; accX[mt][nt][e] = 0.f; }

    #pragma unroll
    for (int l = 0; l < 16; l++) {
        int idx = tid + l*256;
        int t4 = idx >> 10;
        int j = idx & 1023;
        int r = j >> 3, q8 = j & 7;
        const __half* src = ((t4 < 2) ? Wo : Wg) + (size_t)r*CH + (t4 & 1)*64 + q8*8;
        cpa16(hsm + FN_W + t4*HBUF + r*HSTRIDE + q8*8, src);
    }
    {
        const __half* Ub = U0 + (size_t)rb0 * 128 * CH;
        const __half* Xb = X0 + (size_t)rb0 * 128 * CH;
        int r = tid >> 3, q = tid & 7;
        #pragma unroll
        for (int l = 0; l < 4; l++) {
            int rr = r + l*32;
            cpa16(hsm + FN_UX + rr*HSTRIDE + q*8, Ub + (size_t)rr*CH + q*8);
            cpa16(hsm + FN_UX + HBUF + rr*HSTRIDE + q*8, Xb + (size_t)rr*CH + q*8);
        }
    }
    CPA_COMMIT();
    {
        const __half* Ub = U0 + (size_t)rb0 * 128 * CH;
        const __half* Xb = X0 + (size_t)rb0 * 128 * CH;
        int r = tid >> 3, q = tid & 7;
        #pragma unroll
        for (int l = 0; l < 4; l++) {
            int rr = r + l*32;
            cpa16(hsm + FN_UX + 2*HBUF + rr*HSTRIDE + q*8, Ub + (size_t)rr*CH + 64 + q*8);
            cpa16(hsm + FN_UX + 3*HBUF + rr*HSTRIDE + q*8, Xb + (size_t)rr*CH + 64 + q*8);
        }
    }
    CPA_COMMIT();

    int ao = wm*HSTRIDE + a_lane_off(lane);
    int bo = wn*HSTRIDE + b_lane_off(lane);
    int crow = lane >> 2, ccol = (lane & 3) * 2;

    int buf = 0;
    for (int t = 0; t < FN_NCH; t++) {
        CPA_WAIT1();
        __syncthreads();

        if (t + 2 < FN_NCH) {
            int nt2 = t + 2;
            int rb = nt2 >> 1, kc = nt2 & 1;
            int nb = buf + 2; if (nb >= 3) nb -= 3;
            const __half* Ub = U0 + ((size_t)(rb0 + rb) * 128) * CH + kc*64;
            const __half* Xb = X0 + ((size_t)(rb0 + rb) * 128) * CH + kc*64;
            int r = tid >> 3, q = tid & 7;
            #pragma unroll
            for (int l = 0; l < 4; l++) {
                int rr = r + l*32;
                cpa16(hsm + FN_UX + nb*2*HBUF + rr*HSTRIDE + q*8, Ub + (size_t)rr*CH + q*8);
                cpa16(hsm + FN_UX + nb*2*HBUF + HBUF + rr*HSTRIDE + q*8, Xb + (size_t)rr*CH + q*8);
            }
            CPA_COMMIT();
        }

        const __half* cU = hsm + FN_UX + buf*2*HBUF;
        const __half* cX = cU + HBUF;
        const __half* cWo = hsm + FN_W + (t & 1)*HBUF;
        const __half* cWg = hsm + FN_W + 2*HBUF + (t & 1)*HBUF;
        #pragma unroll
        for (int ks = 0; ks < 4; ks++) {
            int kb = ks * 16;
            uint32_t au[4][4], ax[4][4], bo2[2][4], bg2[2][4];
            #pragma unroll
            for (int mt = 0; mt < 4; mt++) {
                ldsm4(au[mt], cU + ao + mt*16*HSTRIDE + kb);
                ldsm4(ax[mt], cX + ao + mt*16*HSTRIDE + kb);
            }
            #pragma unroll
            for (int np = 0; np < 2; np++) {
                ldsm4(bo2[np], cWo + bo + np*16*HSTRIDE + kb);
                ldsm4(bg2[np], cWg + bo + np*16*HSTRIDE + kb);
            }
            #pragma unroll
            for (int mt = 0; mt < 4; mt++)
                #pragma unroll
                for (int nt = 0; nt < 4; nt++) {
                    mma16(accU[mt][nt], au[mt], &bo2[nt>>1][(nt&1)*2]);
                    mma16(accX[mt][nt], ax[mt], &bg2[nt>>1][(nt&1)*2]);
                }
        }

        if (t & 1) {
            size_t i0 = (size_t)(rb0 + (t >> 1)) * 128;
            #pragma unroll
            for (int mt = 0; mt < 4; mt++) {
                #pragma unroll
                for (int nt = 0; nt < 4; nt++) {
                    size_t r1 = i0 + wm + mt*16 + crow;
                    int col = wn + nt*8 + ccol;
                    float2 v0, v1;
                    v0.x = accU[mt][nt][0] * sigm(accX[mt][nt][0]);
                    v0.y = accU[mt][nt][1] * sigm(accX[mt][nt][1]);
                    v1.x = accU[mt][nt][2] * sigm(accX[mt][nt][2]);
                    v1.y = accU[mt][nt][3] * sigm(accX[mt][nt][3]);
                    *(float2*)(out + r1*CH + col) = v0;
                    *(float2*)(out + (r1+8)*CH + col) = v1;
                }
            }
            #pragma unroll
            for (int mt = 0; mt < 4; mt++)
                #pragma unroll
                for (int nt = 0; nt < 4; nt++)
                    #pragma unroll
                    for (int e = 0; e < 4; e++) { accU[mt][nt][e] = 0.f; accX[mt][nt][e] = 0.f; }
        }
        buf++; if (buf >= 3) buf = 0;
    }
}

// ---------------------------------------------------------------- launch
extern "C" void kernel_launch(void* const* d_in, const int* in_sizes, int n_in,
                              void* d_out, int out_size)
{
    const float* pair     = (const float*)d_in[0];
    const float* mask     = (const float*)d_in[1];
    const float* ln1_w    = (const float*)d_in[2];
    const float* ln1_b    = (const float*)d_in[3];
    const float* proj_w   = (const float*)d_in[4];
    const float* gate_w   = (const float*)d_in[5];
    const float* ln2_w    = (const float*)d_in[6];
    const float* ln2_b    = (const float*)d_in[7];
    const float* out_w    = (const float*)d_in[8];
    const float* gating_w = (const float*)d_in[9];
    float* out = (float*)d_out;

    cudaFuncSetAttribute(k_projgate_mma, cudaFuncAttributeMaxDynamicSharedMemorySize, PG_SMEM);
    cudaFuncSetAttribute(k_einsum_mma,   cudaFuncAttributeMaxDynamicSharedMemorySize, DSMEM);
    cudaFuncSetAttribute(k_final_mma,    cudaFuncAttributeMaxDynamicSharedMemorySize, FN_SMEM);

    k_cvtw<<<48, 256>>>(proj_w, gate_w, out_w, gating_w);
    k_ln1<<<RTOT/32, 256>>>(pair, ln1_w, ln1_b);
    k_projgate_mma<<<dim3(4, RTOT/128/PG_ITER), 256, PG_SMEM>>>(mask);
    k_einsum_mma<<<dim3(NTOK/128, NTOK/128, CH), 256, DSMEM>>>();
    k_ln2t<<<RTOT/32, 256>>>(ln2_w, ln2_b);
    k_final_mma<<<RTOT/128/FN_ITER, 256, FN_SMEM>>>(out);
}